// round 1
// baseline (speedup 1.0000x reference)
#include <cuda_runtime.h>
#include <math.h>

#define TT   2048
#define HID  4096
#define NH   32
#define NKV  8
#define HD   128
#define QSZ  (NH * HD)          // 4096
#define KVSZ (NKV * HD)         // 1024
#define QKVO (QSZ + 2 * KVSZ)   // 6144

// ---------------- device scratch (allocation-free) ----------------
__device__ float g_qkv[TT * QKVO];   // qkv projection output
__device__ float g_q[TT * QSZ];      // normed+roped q
__device__ float g_k[TT * KVSZ];     // normed+roped k
__device__ float g_attn[TT * QSZ];   // attention output

// ---------------- SGEMM: C[M,N] = A[M,K] * B[N,K]^T (+bias) ----------------
// 128x128 tile, BK=8, 256 threads, 8x8 per thread, register-staged prefetch.
template <bool HAS_BIAS>
__global__ __launch_bounds__(256) void sgemm_nt(
    const float* __restrict__ A, const float* __restrict__ B,
    const float* __restrict__ bias, float* __restrict__ C,
    int M, int N, int K)
{
    __shared__ float As[8][132];
    __shared__ float Bs[8][132];
    const int tid = threadIdx.x;
    const int tx = tid & 15, ty = tid >> 4;
    const int m0 = blockIdx.y * 128, n0 = blockIdx.x * 128;
    const int lrow = tid >> 1;
    const int lk4  = (tid & 1) * 4;
    const float* Ag = A + (size_t)(m0 + lrow) * K + lk4;
    const float* Bg = B + (size_t)(n0 + lrow) * K + lk4;

    float4 ra = *(const float4*)Ag;
    float4 rb = *(const float4*)Bg;

    float acc[8][8];
#pragma unroll
    for (int i = 0; i < 8; i++)
#pragma unroll
        for (int j = 0; j < 8; j++) acc[i][j] = 0.f;

    for (int kt = 0; kt < K; kt += 8) {
        As[lk4 + 0][lrow] = ra.x; As[lk4 + 1][lrow] = ra.y;
        As[lk4 + 2][lrow] = ra.z; As[lk4 + 3][lrow] = ra.w;
        Bs[lk4 + 0][lrow] = rb.x; Bs[lk4 + 1][lrow] = rb.y;
        Bs[lk4 + 2][lrow] = rb.z; Bs[lk4 + 3][lrow] = rb.w;
        __syncthreads();
        if (kt + 8 < K) {
            ra = *(const float4*)(Ag + kt + 8);
            rb = *(const float4*)(Bg + kt + 8);
        }
#pragma unroll
        for (int kk = 0; kk < 8; kk++) {
            float a[8], b[8];
            *(float4*)&a[0] = *(const float4*)&As[kk][ty * 8];
            *(float4*)&a[4] = *(const float4*)&As[kk][ty * 8 + 4];
            *(float4*)&b[0] = *(const float4*)&Bs[kk][tx * 8];
            *(float4*)&b[4] = *(const float4*)&Bs[kk][tx * 8 + 4];
#pragma unroll
            for (int i = 0; i < 8; i++)
#pragma unroll
                for (int j = 0; j < 8; j++)
                    acc[i][j] += a[i] * b[j];
        }
        __syncthreads();
    }

#pragma unroll
    for (int i = 0; i < 8; i++) {
        const int m = m0 + ty * 8 + i;
#pragma unroll
        for (int j4 = 0; j4 < 2; j4++) {
            const int n = n0 + tx * 8 + j4 * 4;
            float4 v;
            v.x = acc[i][j4 * 4 + 0];
            v.y = acc[i][j4 * 4 + 1];
            v.z = acc[i][j4 * 4 + 2];
            v.w = acc[i][j4 * 4 + 3];
            if (HAS_BIAS) {
                v.x += bias[n + 0]; v.y += bias[n + 1];
                v.z += bias[n + 2]; v.w += bias[n + 3];
            }
            *(float4*)&C[(size_t)m * N + n] = v;
        }
    }
}

// ---------------- per-head RMSNorm + partial RoPE ----------------
// grid (T, 40): heads 0..31 = q, 32..39 = k.  128 threads = one head vector.
__global__ void norm_rope_kernel(const float* __restrict__ qnw,
                                 const float* __restrict__ knw)
{
    const int t = blockIdx.x;
    const int h = blockIdx.y;
    const int d = threadIdx.x;
    const bool is_q = (h < NH);
    const int off = is_q ? (h * HD) : (QSZ + (h - NH) * HD);
    const float x = g_qkv[(size_t)t * QKVO + off + d];

    float s = x * x;
#pragma unroll
    for (int o = 16; o; o >>= 1) s += __shfl_xor_sync(0xffffffffu, s, o);
    __shared__ float red[4];
    if ((d & 31) == 0) red[d >> 5] = s;
    __syncthreads();
    const float sum = red[0] + red[1] + red[2] + red[3];
    const float r = rsqrtf(sum * (1.0f / HD) + 1e-5f);
    const float y = x * r * (is_q ? qnw[d] : knw[d]);

    __shared__ float sh[HD];
    sh[d] = y;
    __syncthreads();

    float outv = y;
    if (d < 64) {
        const int i = d & 31;                            // freq index 0..31
        const float inv_freq = powf(10000.0f, -(float)i * (1.0f / 32.0f));
        const float ang = (float)t * inv_freq;
        float sn, cs;
        sincosf(ang, &sn, &cs);
        if (d < 32) outv = sh[d] * cs - sh[d + 32] * sn;
        else        outv = sh[d] * cs + sh[d - 32] * sn;
    }
    if (is_q) g_q[(size_t)t * QSZ + h * HD + d] = outv;
    else      g_k[(size_t)t * KVSZ + (h - NH) * HD + d] = outv;
}

// ---------------- causal flash attention (fp32) ----------------
#define AQS 132   // padded stride for 128-dim rows (float4 aligned)
#define APS 68    // padded stride for 64-col score rows
#define ATTN_SMEM ((2 * 64 * AQS + 64 * APS) * 4)

__global__ __launch_bounds__(256) void attn_kernel()
{
    extern __shared__ float smem[];
    float* Qs  = smem;                // 64 x AQS
    float* KVs = smem + 64 * AQS;     // 64 x AQS  (K, then reused for V)
    float* Ps  = smem + 2 * 64 * AQS; // 64 x APS

    const int tid = threadIdx.x;
    const int bx = blockIdx.x;        // q tile (64 rows)
    const int h  = blockIdx.y;        // q head
    const int kvh = h >> 2;           // kv head (32/8 = 4 reps)
    const int tx = tid & 15, ty = tid >> 4;
    const int row = tid >> 2, cq = tid & 3;
    const float scale = 0.0883883476483184f;  // 1/sqrt(128)

    // load Q tile
    for (int i = tid; i < 64 * 32; i += 256) {
        const int r = i >> 5, c4 = (i & 31) << 2;
        float4 v = *(const float4*)&g_q[(size_t)(bx * 64 + r) * QSZ + h * HD + c4];
        *(float4*)&Qs[r * AQS + c4] = v;
    }

    float m_r = -1e30f, l_r = 0.f;
    float acc[32];
#pragma unroll
    for (int c = 0; c < 32; c++) acc[c] = 0.f;

    for (int kt = 0; kt <= bx; kt++) {
        __syncthreads();   // prev-iter V reads done; Q visible on first iter
        // load K tile
        for (int i = tid; i < 64 * 32; i += 256) {
            const int r = i >> 5, c4 = (i & 31) << 2;
            float4 v = *(const float4*)&g_k[(size_t)(kt * 64 + r) * KVSZ + kvh * HD + c4];
            *(float4*)&KVs[r * AQS + c4] = v;
        }
        __syncthreads();

        // S = Q K^T : 4x4 per thread
        float s[4][4];
#pragma unroll
        for (int i = 0; i < 4; i++)
#pragma unroll
            for (int j = 0; j < 4; j++) s[i][j] = 0.f;

#pragma unroll 8
        for (int kk = 0; kk < HD; kk += 4) {
            float4 a[4], b[4];
#pragma unroll
            for (int i = 0; i < 4; i++)
                a[i] = *(const float4*)&Qs[(ty * 4 + i) * AQS + kk];
#pragma unroll
            for (int j = 0; j < 4; j++)
                b[j] = *(const float4*)&KVs[(tx * 4 + j) * AQS + kk];
#pragma unroll
            for (int i = 0; i < 4; i++)
#pragma unroll
                for (int j = 0; j < 4; j++)
                    s[i][j] += a[i].x * b[j].x + a[i].y * b[j].y +
                               a[i].z * b[j].z + a[i].w * b[j].w;
        }
        __syncthreads();   // done reading K

        // load V tile into same buffer
        for (int i = tid; i < 64 * 32; i += 256) {
            const int r = i >> 5, c4 = (i & 31) << 2;
            float4 v = *(const float4*)&g_qkv[(size_t)(kt * 64 + r) * QKVO +
                                              QSZ + KVSZ + kvh * HD + c4];
            *(float4*)&KVs[r * AQS + c4] = v;
        }

        // write masked, scaled scores
        const bool diag = (kt == bx);
#pragma unroll
        for (int i = 0; i < 4; i++) {
            const int ri = ty * 4 + i;
#pragma unroll
            for (int j = 0; j < 4; j++) {
                float v = s[i][j] * scale;
                if (diag && (tx * 4 + j) > ri) v = -1e30f;
                Ps[ri * APS + tx * 4 + j] = v;
            }
        }
        __syncthreads();   // V loaded + scores visible

        // online softmax: 4 threads per row
        float mx = -1e30f;
#pragma unroll
        for (int k2 = 0; k2 < 16; k2++)
            mx = fmaxf(mx, Ps[row * APS + cq + 4 * k2]);
        mx = fmaxf(mx, __shfl_xor_sync(0xffffffffu, mx, 1));
        mx = fmaxf(mx, __shfl_xor_sync(0xffffffffu, mx, 2));
        const float m_new = fmaxf(m_r, mx);
        const float corr = __expf(m_r - m_new);
        float rs = 0.f;
#pragma unroll
        for (int k2 = 0; k2 < 16; k2++) {
            const int idx = row * APS + cq + 4 * k2;
            const float p = __expf(Ps[idx] - m_new);
            Ps[idx] = p;
            rs += p;
        }
        rs += __shfl_xor_sync(0xffffffffu, rs, 1);
        rs += __shfl_xor_sync(0xffffffffu, rs, 2);
        l_r = l_r * corr + rs;
        m_r = m_new;
#pragma unroll
        for (int c = 0; c < 32; c++) acc[c] *= corr;
        __syncwarp();   // exp'd Ps row shared among the 4 sibling lanes

        // O += P V   (thread owns row, 32 interleaved cols: cq*4 + u + 16*c8)
#pragma unroll 8
        for (int j = 0; j < 64; j++) {
            const float p = Ps[row * APS + j];
#pragma unroll
            for (int c8 = 0; c8 < 8; c8++) {
                float4 v = *(const float4*)&KVs[j * AQS + cq * 4 + c8 * 16];
                acc[c8 * 4 + 0] += p * v.x;
                acc[c8 * 4 + 1] += p * v.y;
                acc[c8 * 4 + 2] += p * v.z;
                acc[c8 * 4 + 3] += p * v.w;
            }
        }
    }

    const float inv_l = 1.0f / l_r;
    const int grow = bx * 64 + row;
#pragma unroll
    for (int c8 = 0; c8 < 8; c8++) {
        float4 v;
        v.x = acc[c8 * 4 + 0] * inv_l;
        v.y = acc[c8 * 4 + 1] * inv_l;
        v.z = acc[c8 * 4 + 2] * inv_l;
        v.w = acc[c8 * 4 + 3] * inv_l;
        *(float4*)&g_attn[(size_t)grow * QSZ + h * HD + cq * 4 + c8 * 16] = v;
    }
}

// ---------------- launch ----------------
extern "C" void kernel_launch(void* const* d_in, const int* in_sizes, int n_in,
                              void* d_out, int out_size)
{
    // inputs: 0 positions(int64, == arange(T)), 1 hidden, 2 w_qkv, 3 b_qkv,
    //         4 q_norm_w, 5 k_norm_w, 6 w_o
    const float* hidden = (const float*)d_in[1];
    const float* w_qkv  = (const float*)d_in[2];
    const float* b_qkv  = (const float*)d_in[3];
    const float* qnw    = (const float*)d_in[4];
    const float* knw    = (const float*)d_in[5];
    const float* w_o    = (const float*)d_in[6];
    float* out = (float*)d_out;

    float *qkv_s, *attn_s;
    cudaGetSymbolAddress((void**)&qkv_s, g_qkv);
    cudaGetSymbolAddress((void**)&attn_s, g_attn);

    // 1) QKV projection + bias
    sgemm_nt<true><<<dim3(QKVO / 128, TT / 128), 256>>>(
        hidden, w_qkv, b_qkv, qkv_s, TT, QKVO, HID);

    // 2) RMSNorm + RoPE for q and k heads
    norm_rope_kernel<<<dim3(TT, NH + NKV), HD>>>(qnw, knw);

    // 3) causal GQA flash attention
    cudaFuncSetAttribute(attn_kernel,
                         cudaFuncAttributeMaxDynamicSharedMemorySize, ATTN_SMEM);
    attn_kernel<<<dim3(TT / 64, NH), 256, ATTN_SMEM>>>();

    // 4) output projection
    sgemm_nt<false><<<dim3(HID / 128, TT / 128), 256>>>(
        attn_s, w_o, nullptr, out, TT, HID, HID);
}

// round 2
// speedup vs baseline: 1.6127x; 1.6127x over previous
#include <cuda_runtime.h>
#include <math.h>
#include <stdint.h>

#define TT   2048
#define HID  4096
#define NH   32
#define NKV  8
#define HD   128
#define QSZ  (NH * HD)          // 4096
#define KVSZ (NKV * HD)         // 1024
#define QKVO (QSZ + 2 * KVSZ)   // 6144

// ---------------- device scratch (allocation-free) ----------------
__device__ float g_qkv[TT * QKVO];   // qkv projection output
__device__ float g_q[TT * QSZ];      // normed+roped q
__device__ float g_k[TT * KVSZ];     // normed+roped k
__device__ float g_attn[TT * QSZ];   // attention output

// ---------------- tf32 helpers ----------------
__device__ __forceinline__ uint32_t f2tf32(float x) {
    uint32_t u;
    asm("cvt.rna.tf32.f32 %0, %1;" : "=r"(u) : "f"(x));
    return u;
}

__device__ __forceinline__ void mma_tf32(float* d, const uint32_t* a, const uint32_t* b) {
    asm volatile(
        "mma.sync.aligned.m16n8k8.row.col.f32.tf32.tf32.f32 "
        "{%0,%1,%2,%3},{%4,%5,%6,%7},{%8,%9},{%0,%1,%2,%3};"
        : "+f"(d[0]), "+f"(d[1]), "+f"(d[2]), "+f"(d[3])
        : "r"(a[0]), "r"(a[1]), "r"(a[2]), "r"(a[3]), "r"(b[0]), "r"(b[1]));
}

// ---------------- tf32 tensor-core GEMM: C[M,N] = A[M,K] * B[N,K]^T (+bias) --
// 128x128 CTA tile, BK=16, 256 threads = 8 warps (2x4), warp tile 64x32,
// mma m16n8k8 tf32, smem pad 20 (conflict-free fragment loads).
template <bool HAS_BIAS>
__global__ __launch_bounds__(256, 2) void gemm_tf32_nt(
    const float* __restrict__ A, const float* __restrict__ B,
    const float* __restrict__ bias, float* __restrict__ C,
    int M, int N, int K)
{
    __shared__ uint32_t As[128][20];
    __shared__ uint32_t Bs[128][20];

    const int tid  = threadIdx.x;
    const int lane = tid & 31;
    const int warp = tid >> 5;
    const int wm = (warp >> 2) * 64;      // warp row offset (0 / 64)
    const int wn = (warp & 3) * 32;       // warp col offset
    const int g    = lane >> 2;           // group id 0..7
    const int ktid = lane & 3;            // thread-in-group 0..3

    const int m0 = blockIdx.y * 128, n0 = blockIdx.x * 128;

    const int lr  = tid >> 2;             // 0..63 (and +64)
    const int lc4 = (tid & 3) * 4;        // k offset 0,4,8,12

    const float* Ag0 = A + (size_t)(m0 + lr) * K + lc4;
    const float* Ag1 = A + (size_t)(m0 + lr + 64) * K + lc4;
    const float* Bg0 = B + (size_t)(n0 + lr) * K + lc4;
    const float* Bg1 = B + (size_t)(n0 + lr + 64) * K + lc4;

    float4 ra0 = *(const float4*)Ag0;
    float4 ra1 = *(const float4*)Ag1;
    float4 rb0 = *(const float4*)Bg0;
    float4 rb1 = *(const float4*)Bg1;

    float acc[4][4][4];
#pragma unroll
    for (int i = 0; i < 4; i++)
#pragma unroll
        for (int j = 0; j < 4; j++)
#pragma unroll
            for (int c = 0; c < 4; c++) acc[i][j][c] = 0.f;

    for (int kt = 0; kt < K; kt += 16) {
        // store (fp32 -> tf32) to smem
        As[lr][lc4 + 0] = f2tf32(ra0.x); As[lr][lc4 + 1] = f2tf32(ra0.y);
        As[lr][lc4 + 2] = f2tf32(ra0.z); As[lr][lc4 + 3] = f2tf32(ra0.w);
        As[lr + 64][lc4 + 0] = f2tf32(ra1.x); As[lr + 64][lc4 + 1] = f2tf32(ra1.y);
        As[lr + 64][lc4 + 2] = f2tf32(ra1.z); As[lr + 64][lc4 + 3] = f2tf32(ra1.w);
        Bs[lr][lc4 + 0] = f2tf32(rb0.x); Bs[lr][lc4 + 1] = f2tf32(rb0.y);
        Bs[lr][lc4 + 2] = f2tf32(rb0.z); Bs[lr][lc4 + 3] = f2tf32(rb0.w);
        Bs[lr + 64][lc4 + 0] = f2tf32(rb1.x); Bs[lr + 64][lc4 + 1] = f2tf32(rb1.y);
        Bs[lr + 64][lc4 + 2] = f2tf32(rb1.z); Bs[lr + 64][lc4 + 3] = f2tf32(rb1.w);
        __syncthreads();

        if (kt + 16 < K) {
            ra0 = *(const float4*)(Ag0 + kt + 16);
            ra1 = *(const float4*)(Ag1 + kt + 16);
            rb0 = *(const float4*)(Bg0 + kt + 16);
            rb1 = *(const float4*)(Bg1 + kt + 16);
        }

#pragma unroll
        for (int s = 0; s < 16; s += 8) {
            uint32_t af[4][4], bf[4][2];
#pragma unroll
            for (int mi = 0; mi < 4; mi++) {
                const int row = wm + mi * 16 + g;
                af[mi][0] = As[row][s + ktid];
                af[mi][1] = As[row + 8][s + ktid];
                af[mi][2] = As[row][s + ktid + 4];
                af[mi][3] = As[row + 8][s + ktid + 4];
            }
#pragma unroll
            for (int ni = 0; ni < 4; ni++) {
                const int col = wn + ni * 8 + g;
                bf[ni][0] = Bs[col][s + ktid];
                bf[ni][1] = Bs[col][s + ktid + 4];
            }
#pragma unroll
            for (int mi = 0; mi < 4; mi++)
#pragma unroll
                for (int ni = 0; ni < 4; ni++)
                    mma_tf32(acc[mi][ni], af[mi], bf[ni]);
        }
        __syncthreads();
    }

    // epilogue
#pragma unroll
    for (int mi = 0; mi < 4; mi++) {
        const int row = m0 + wm + mi * 16 + g;
#pragma unroll
        for (int ni = 0; ni < 4; ni++) {
            const int col = n0 + wn + ni * 8 + 2 * ktid;
            float b0 = 0.f, b1 = 0.f;
            if (HAS_BIAS) { b0 = bias[col]; b1 = bias[col + 1]; }
            float2 v0 = make_float2(acc[mi][ni][0] + b0, acc[mi][ni][1] + b1);
            float2 v1 = make_float2(acc[mi][ni][2] + b0, acc[mi][ni][3] + b1);
            *(float2*)&C[(size_t)row * N + col] = v0;
            *(float2*)&C[(size_t)(row + 8) * N + col] = v1;
        }
    }
}

// ---------------- per-head RMSNorm + partial RoPE ----------------
__global__ void norm_rope_kernel(const float* __restrict__ qnw,
                                 const float* __restrict__ knw)
{
    const int t = blockIdx.x;
    const int h = blockIdx.y;
    const int d = threadIdx.x;
    const bool is_q = (h < NH);
    const int off = is_q ? (h * HD) : (QSZ + (h - NH) * HD);
    const float x = g_qkv[(size_t)t * QKVO + off + d];

    float s = x * x;
#pragma unroll
    for (int o = 16; o; o >>= 1) s += __shfl_xor_sync(0xffffffffu, s, o);
    __shared__ float red[4];
    if ((d & 31) == 0) red[d >> 5] = s;
    __syncthreads();
    const float sum = red[0] + red[1] + red[2] + red[3];
    const float r = rsqrtf(sum * (1.0f / HD) + 1e-5f);
    const float y = x * r * (is_q ? qnw[d] : knw[d]);

    __shared__ float sh[HD];
    sh[d] = y;
    __syncthreads();

    float outv = y;
    if (d < 64) {
        const int i = d & 31;
        const float inv_freq = powf(10000.0f, -(float)i * (1.0f / 32.0f));
        const float ang = (float)t * inv_freq;
        float sn, cs;
        sincosf(ang, &sn, &cs);
        if (d < 32) outv = sh[d] * cs - sh[d + 32] * sn;
        else        outv = sh[d] * cs + sh[d - 32] * sn;
    }
    if (is_q) g_q[(size_t)t * QSZ + h * HD + d] = outv;
    else      g_k[(size_t)t * KVSZ + (h - NH) * HD + d] = outv;
}

// ---------------- causal flash attention (fp32) ----------------
#define AQS 132
#define APS 68
#define ATTN_SMEM ((2 * 64 * AQS + 64 * APS) * 4)

__global__ __launch_bounds__(256) void attn_kernel()
{
    extern __shared__ float smem[];
    float* Qs  = smem;
    float* KVs = smem + 64 * AQS;
    float* Ps  = smem + 2 * 64 * AQS;

    const int tid = threadIdx.x;
    const int bx = blockIdx.x;
    const int h  = blockIdx.y;
    const int kvh = h >> 2;
    const int tx = tid & 15, ty = tid >> 4;
    const int row = tid >> 2, cq = tid & 3;
    const float scale = 0.0883883476483184f;

    for (int i = tid; i < 64 * 32; i += 256) {
        const int r = i >> 5, c4 = (i & 31) << 2;
        float4 v = *(const float4*)&g_q[(size_t)(bx * 64 + r) * QSZ + h * HD + c4];
        *(float4*)&Qs[r * AQS + c4] = v;
    }

    float m_r = -1e30f, l_r = 0.f;
    float acc[32];
#pragma unroll
    for (int c = 0; c < 32; c++) acc[c] = 0.f;

    for (int kt = 0; kt <= bx; kt++) {
        __syncthreads();
        for (int i = tid; i < 64 * 32; i += 256) {
            const int r = i >> 5, c4 = (i & 31) << 2;
            float4 v = *(const float4*)&g_k[(size_t)(kt * 64 + r) * KVSZ + kvh * HD + c4];
            *(float4*)&KVs[r * AQS + c4] = v;
        }
        __syncthreads();

        float s[4][4];
#pragma unroll
        for (int i = 0; i < 4; i++)
#pragma unroll
            for (int j = 0; j < 4; j++) s[i][j] = 0.f;

#pragma unroll 8
        for (int kk = 0; kk < HD; kk += 4) {
            float4 a[4], b[4];
#pragma unroll
            for (int i = 0; i < 4; i++)
                a[i] = *(const float4*)&Qs[(ty * 4 + i) * AQS + kk];
#pragma unroll
            for (int j = 0; j < 4; j++)
                b[j] = *(const float4*)&KVs[(tx * 4 + j) * AQS + kk];
#pragma unroll
            for (int i = 0; i < 4; i++)
#pragma unroll
                for (int j = 0; j < 4; j++)
                    s[i][j] += a[i].x * b[j].x + a[i].y * b[j].y +
                               a[i].z * b[j].z + a[i].w * b[j].w;
        }
        __syncthreads();

        for (int i = tid; i < 64 * 32; i += 256) {
            const int r = i >> 5, c4 = (i & 31) << 2;
            float4 v = *(const float4*)&g_qkv[(size_t)(kt * 64 + r) * QKVO +
                                              QSZ + KVSZ + kvh * HD + c4];
            *(float4*)&KVs[r * AQS + c4] = v;
        }

        const bool diag = (kt == bx);
#pragma unroll
        for (int i = 0; i < 4; i++) {
            const int ri = ty * 4 + i;
#pragma unroll
            for (int j = 0; j < 4; j++) {
                float v = s[i][j] * scale;
                if (diag && (tx * 4 + j) > ri) v = -1e30f;
                Ps[ri * APS + tx * 4 + j] = v;
            }
        }
        __syncthreads();

        float mx = -1e30f;
#pragma unroll
        for (int k2 = 0; k2 < 16; k2++)
            mx = fmaxf(mx, Ps[row * APS + cq + 4 * k2]);
        mx = fmaxf(mx, __shfl_xor_sync(0xffffffffu, mx, 1));
        mx = fmaxf(mx, __shfl_xor_sync(0xffffffffu, mx, 2));
        const float m_new = fmaxf(m_r, mx);
        const float corr = __expf(m_r - m_new);
        float rs = 0.f;
#pragma unroll
        for (int k2 = 0; k2 < 16; k2++) {
            const int idx = row * APS + cq + 4 * k2;
            const float p = __expf(Ps[idx] - m_new);
            Ps[idx] = p;
            rs += p;
        }
        rs += __shfl_xor_sync(0xffffffffu, rs, 1);
        rs += __shfl_xor_sync(0xffffffffu, rs, 2);
        l_r = l_r * corr + rs;
        m_r = m_new;
#pragma unroll
        for (int c = 0; c < 32; c++) acc[c] *= corr;
        __syncwarp();

#pragma unroll 8
        for (int j = 0; j < 64; j++) {
            const float p = Ps[row * APS + j];
#pragma unroll
            for (int c8 = 0; c8 < 8; c8++) {
                float4 v = *(const float4*)&KVs[j * AQS + cq * 4 + c8 * 16];
                acc[c8 * 4 + 0] += p * v.x;
                acc[c8 * 4 + 1] += p * v.y;
                acc[c8 * 4 + 2] += p * v.z;
                acc[c8 * 4 + 3] += p * v.w;
            }
        }
    }

    const float inv_l = 1.0f / l_r;
    const int grow = bx * 64 + row;
#pragma unroll
    for (int c8 = 0; c8 < 8; c8++) {
        float4 v;
        v.x = acc[c8 * 4 + 0] * inv_l;
        v.y = acc[c8 * 4 + 1] * inv_l;
        v.z = acc[c8 * 4 + 2] * inv_l;
        v.w = acc[c8 * 4 + 3] * inv_l;
        *(float4*)&g_attn[(size_t)grow * QSZ + h * HD + cq * 4 + c8 * 16] = v;
    }
}

// ---------------- launch ----------------
extern "C" void kernel_launch(void* const* d_in, const int* in_sizes, int n_in,
                              void* d_out, int out_size)
{
    const float* hidden = (const float*)d_in[1];
    const float* w_qkv  = (const float*)d_in[2];
    const float* b_qkv  = (const float*)d_in[3];
    const float* qnw    = (const float*)d_in[4];
    const float* knw    = (const float*)d_in[5];
    const float* w_o    = (const float*)d_in[6];
    float* out = (float*)d_out;

    float *qkv_s, *attn_s;
    cudaGetSymbolAddress((void**)&qkv_s, g_qkv);
    cudaGetSymbolAddress((void**)&attn_s, g_attn);

    // 1) QKV projection + bias (tf32 tensor cores)
    gemm_tf32_nt<true><<<dim3(QKVO / 128, TT / 128), 256>>>(
        hidden, w_qkv, b_qkv, qkv_s, TT, QKVO, HID);

    // 2) RMSNorm + RoPE
    norm_rope_kernel<<<dim3(TT, NH + NKV), HD>>>(qnw, knw);

    // 3) causal GQA flash attention
    cudaFuncSetAttribute(attn_kernel,
                         cudaFuncAttributeMaxDynamicSharedMemorySize, ATTN_SMEM);
    attn_kernel<<<dim3(TT / 64, NH), 256, ATTN_SMEM>>>();

    // 4) output projection (tf32 tensor cores)
    gemm_tf32_nt<false><<<dim3(HID / 128, TT / 128), 256>>>(
        attn_s, w_o, nullptr, out, TT, HID, HID);
}

// round 3
// speedup vs baseline: 3.3274x; 2.0633x over previous
#include <cuda_runtime.h>
#include <math.h>
#include <stdint.h>

#define TT   2048
#define HID  4096
#define NH   32
#define NKV  8
#define HD   128
#define QSZ  (NH * HD)          // 4096
#define KVSZ (NKV * HD)         // 1024
#define QKVO (QSZ + 2 * KVSZ)   // 6144

// ---------------- device scratch (allocation-free) ----------------
__device__ float g_qkv[TT * QKVO];
__device__ float g_q[TT * QSZ];
__device__ float g_k[TT * KVSZ];
__device__ float g_attn[TT * QSZ];

// ---------------- tf32 helpers ----------------
__device__ __forceinline__ uint32_t f2tf32(float x) {
    uint32_t u;
    asm("cvt.rna.tf32.f32 %0, %1;" : "=r"(u) : "f"(x));
    return u;
}

__device__ __forceinline__ void mma_tf32(float* d, const uint32_t* a, const uint32_t* b) {
    asm volatile(
        "mma.sync.aligned.m16n8k8.row.col.f32.tf32.tf32.f32 "
        "{%0,%1,%2,%3},{%4,%5,%6,%7},{%8,%9},{%0,%1,%2,%3};"
        : "+f"(d[0]), "+f"(d[1]), "+f"(d[2]), "+f"(d[3])
        : "r"(a[0]), "r"(a[1]), "r"(a[2]), "r"(a[3]), "r"(b[0]), "r"(b[1]));
}

// ---------------- tf32 GEMM: C[M,N] = A[M,K]*B[N,K]^T (+bias) ---------------
// 128x128 tile, BK=16, 8 warps (2x4), warp 64x32, double-buffered smem,
// single __syncthreads per k-tile.
template <bool HAS_BIAS>
__global__ __launch_bounds__(256, 2) void gemm_tf32_nt(
    const float* __restrict__ A, const float* __restrict__ B,
    const float* __restrict__ bias, float* __restrict__ C,
    int M, int N, int K)
{
    __shared__ uint32_t As[2][128][20];
    __shared__ uint32_t Bs[2][128][20];

    const int tid  = threadIdx.x;
    const int lane = tid & 31;
    const int warp = tid >> 5;
    const int wm = (warp >> 2) * 64;
    const int wn = (warp & 3) * 32;
    const int g    = lane >> 2;
    const int ktid = lane & 3;
    const int m0 = blockIdx.y * 128, n0 = blockIdx.x * 128;
    const int lr  = tid >> 2;
    const int lc4 = (tid & 3) * 4;

    const float* Ag0 = A + (size_t)(m0 + lr) * K + lc4;
    const float* Ag1 = A + (size_t)(m0 + lr + 64) * K + lc4;
    const float* Bg0 = B + (size_t)(n0 + lr) * K + lc4;
    const float* Bg1 = B + (size_t)(n0 + lr + 64) * K + lc4;

    float acc[4][4][4];
#pragma unroll
    for (int i = 0; i < 4; i++)
#pragma unroll
        for (int j = 0; j < 4; j++)
#pragma unroll
            for (int c = 0; c < 4; c++) acc[i][j][c] = 0.f;

    float4 ra0 = *(const float4*)Ag0;
    float4 ra1 = *(const float4*)Ag1;
    float4 rb0 = *(const float4*)Bg0;
    float4 rb1 = *(const float4*)Bg1;

#define STORE_STAGE(buf)                                                      \
    do {                                                                      \
        As[buf][lr][lc4 + 0] = f2tf32(ra0.x); As[buf][lr][lc4 + 1] = f2tf32(ra0.y); \
        As[buf][lr][lc4 + 2] = f2tf32(ra0.z); As[buf][lr][lc4 + 3] = f2tf32(ra0.w); \
        As[buf][lr + 64][lc4 + 0] = f2tf32(ra1.x); As[buf][lr + 64][lc4 + 1] = f2tf32(ra1.y); \
        As[buf][lr + 64][lc4 + 2] = f2tf32(ra1.z); As[buf][lr + 64][lc4 + 3] = f2tf32(ra1.w); \
        Bs[buf][lr][lc4 + 0] = f2tf32(rb0.x); Bs[buf][lr][lc4 + 1] = f2tf32(rb0.y); \
        Bs[buf][lr][lc4 + 2] = f2tf32(rb0.z); Bs[buf][lr][lc4 + 3] = f2tf32(rb0.w); \
        Bs[buf][lr + 64][lc4 + 0] = f2tf32(rb1.x); Bs[buf][lr + 64][lc4 + 1] = f2tf32(rb1.y); \
        Bs[buf][lr + 64][lc4 + 2] = f2tf32(rb1.z); Bs[buf][lr + 64][lc4 + 3] = f2tf32(rb1.w); \
    } while (0)

    STORE_STAGE(0);
    __syncthreads();
    ra0 = *(const float4*)(Ag0 + 16);
    ra1 = *(const float4*)(Ag1 + 16);
    rb0 = *(const float4*)(Bg0 + 16);
    rb1 = *(const float4*)(Bg1 + 16);

    int cur = 0;
    for (int kt = 0; kt < K; kt += 16) {
        if (kt + 16 < K) STORE_STAGE(cur ^ 1);
        if (kt + 32 < K) {
            ra0 = *(const float4*)(Ag0 + kt + 32);
            ra1 = *(const float4*)(Ag1 + kt + 32);
            rb0 = *(const float4*)(Bg0 + kt + 32);
            rb1 = *(const float4*)(Bg1 + kt + 32);
        }
#pragma unroll
        for (int s = 0; s < 16; s += 8) {
            uint32_t af[4][4], bf[4][2];
#pragma unroll
            for (int mi = 0; mi < 4; mi++) {
                const int row = wm + mi * 16 + g;
                af[mi][0] = As[cur][row][s + ktid];
                af[mi][1] = As[cur][row + 8][s + ktid];
                af[mi][2] = As[cur][row][s + ktid + 4];
                af[mi][3] = As[cur][row + 8][s + ktid + 4];
            }
#pragma unroll
            for (int ni = 0; ni < 4; ni++) {
                const int col = wn + ni * 8 + g;
                bf[ni][0] = Bs[cur][col][s + ktid];
                bf[ni][1] = Bs[cur][col][s + ktid + 4];
            }
#pragma unroll
            for (int mi = 0; mi < 4; mi++)
#pragma unroll
                for (int ni = 0; ni < 4; ni++)
                    mma_tf32(acc[mi][ni], af[mi], bf[ni]);
        }
        __syncthreads();
        cur ^= 1;
    }

#pragma unroll
    for (int mi = 0; mi < 4; mi++) {
        const int row = m0 + wm + mi * 16 + g;
#pragma unroll
        for (int ni = 0; ni < 4; ni++) {
            const int col = n0 + wn + ni * 8 + 2 * ktid;
            float b0 = 0.f, b1 = 0.f;
            if (HAS_BIAS) { b0 = bias[col]; b1 = bias[col + 1]; }
            float2 v0 = make_float2(acc[mi][ni][0] + b0, acc[mi][ni][1] + b1);
            float2 v1 = make_float2(acc[mi][ni][2] + b0, acc[mi][ni][3] + b1);
            *(float2*)&C[(size_t)row * N + col] = v0;
            *(float2*)&C[(size_t)(row + 8) * N + col] = v1;
        }
    }
#undef STORE_STAGE
}

// ---------------- per-head RMSNorm + partial RoPE ----------------
__global__ void norm_rope_kernel(const float* __restrict__ qnw,
                                 const float* __restrict__ knw)
{
    const int t = blockIdx.x;
    const int h = blockIdx.y;
    const int d = threadIdx.x;
    const bool is_q = (h < NH);
    const int off = is_q ? (h * HD) : (QSZ + (h - NH) * HD);
    const float x = g_qkv[(size_t)t * QKVO + off + d];

    float s = x * x;
#pragma unroll
    for (int o = 16; o; o >>= 1) s += __shfl_xor_sync(0xffffffffu, s, o);
    __shared__ float red[4];
    if ((d & 31) == 0) red[d >> 5] = s;
    __syncthreads();
    const float sum = red[0] + red[1] + red[2] + red[3];
    const float r = rsqrtf(sum * (1.0f / HD) + 1e-5f);
    const float y = x * r * (is_q ? qnw[d] : knw[d]);

    __shared__ float sh[HD];
    sh[d] = y;
    __syncthreads();

    float outv = y;
    if (d < 64) {
        const int i = d & 31;
        const float inv_freq = powf(10000.0f, -(float)i * (1.0f / 32.0f));
        const float ang = (float)t * inv_freq;
        float sn, cs;
        sincosf(ang, &sn, &cs);
        if (d < 32) outv = sh[d] * cs - sh[d + 32] * sn;
        else        outv = sh[d] * cs + sh[d - 32] * sn;
    }
    if (is_q) g_q[(size_t)t * QSZ + h * HD + d] = outv;
    else      g_k[(size_t)t * KVSZ + (h - NH) * HD + d] = outv;
}

// ---------------- tensor-core causal flash attention (tf32) ----------------
// 64 q-rows x 64 keys per tile, 4 warps x 16 q-rows, mma m16n8k8.
#define QS_STRIDE 132
#define PS_STRIDE 68
#define ATTN_SMEM ((2 * 64 * QS_STRIDE + 64 * PS_STRIDE) * 4)

__global__ __launch_bounds__(128, 2) void attn_tc_kernel()
{
    extern __shared__ uint32_t smem_u[];
    uint32_t* Qs  = smem_u;                       // [64][132] tf32 (pre-scaled)
    uint32_t* KVs = smem_u + 64 * QS_STRIDE;      // [64][132] tf32 (K then V)
    uint32_t* Ps  = smem_u + 2 * 64 * QS_STRIDE;  // [64][68]  tf32

    const int tid  = threadIdx.x;
    const int lane = tid & 31;
    const int warp = tid >> 5;
    const int g    = lane >> 2;
    const int ktid = lane & 3;
    const int wq0  = warp * 16;
    const int bx = blockIdx.x, h = blockIdx.y, kvh = h >> 2;
    const float scale = 0.0883883476483184f;  // 1/sqrt(128)

    // Q tile (scale folded into tf32 conversion)
    for (int i = tid; i < 2048; i += 128) {
        const int r = i >> 5, c4 = (i & 31) << 2;
        float4 v = *(const float4*)&g_q[(size_t)(bx * 64 + r) * QSZ + h * HD + c4];
        uint32_t* dst = &Qs[r * QS_STRIDE + c4];
        dst[0] = f2tf32(v.x * scale); dst[1] = f2tf32(v.y * scale);
        dst[2] = f2tf32(v.z * scale); dst[3] = f2tf32(v.w * scale);
    }

    float m0 = -1e30f, m1 = -1e30f, l0 = 0.f, l1 = 0.f;
    float acc_o[16][4];
#pragma unroll
    for (int nb = 0; nb < 16; nb++)
#pragma unroll
        for (int c = 0; c < 4; c++) acc_o[nb][c] = 0.f;

    for (int kt = 0; kt <= bx; kt++) {
        __syncthreads();   // prev PV done with KVs; Q visible on first iter
        for (int i = tid; i < 2048; i += 128) {
            const int r = i >> 5, c4 = (i & 31) << 2;
            float4 v = *(const float4*)&g_k[(size_t)(kt * 64 + r) * KVSZ + kvh * HD + c4];
            uint32_t* dst = &KVs[r * QS_STRIDE + c4];
            dst[0] = f2tf32(v.x); dst[1] = f2tf32(v.y);
            dst[2] = f2tf32(v.z); dst[3] = f2tf32(v.w);
        }
        __syncthreads();

        // S = Q K^T
        float s[8][4];
#pragma unroll
        for (int nb = 0; nb < 8; nb++)
#pragma unroll
            for (int c = 0; c < 4; c++) s[nb][c] = 0.f;

#pragma unroll
        for (int kb = 0; kb < 16; kb++) {
            uint32_t a[4];
            a[0] = Qs[(wq0 + g) * QS_STRIDE + kb * 8 + ktid];
            a[1] = Qs[(wq0 + g + 8) * QS_STRIDE + kb * 8 + ktid];
            a[2] = Qs[(wq0 + g) * QS_STRIDE + kb * 8 + ktid + 4];
            a[3] = Qs[(wq0 + g + 8) * QS_STRIDE + kb * 8 + ktid + 4];
#pragma unroll
            for (int nb = 0; nb < 8; nb++) {
                uint32_t b[2];
                b[0] = KVs[(nb * 8 + g) * QS_STRIDE + kb * 8 + ktid];
                b[1] = KVs[(nb * 8 + g) * QS_STRIDE + kb * 8 + ktid + 4];
                mma_tf32(s[nb], a, b);
            }
        }

        // causal mask on diagonal tile
        if (kt == bx) {
            const int r0 = wq0 + g, r1 = r0 + 8;
#pragma unroll
            for (int nb = 0; nb < 8; nb++) {
                const int c = nb * 8 + 2 * ktid;
                if (c     > r0) s[nb][0] = -1e30f;
                if (c + 1 > r0) s[nb][1] = -1e30f;
                if (c     > r1) s[nb][2] = -1e30f;
                if (c + 1 > r1) s[nb][3] = -1e30f;
            }
        }

        // online softmax (rows g and g+8; 4 lanes per row -> xor 1,2)
        float mx0 = -1e30f, mx1 = -1e30f;
#pragma unroll
        for (int nb = 0; nb < 8; nb++) {
            mx0 = fmaxf(mx0, fmaxf(s[nb][0], s[nb][1]));
            mx1 = fmaxf(mx1, fmaxf(s[nb][2], s[nb][3]));
        }
        mx0 = fmaxf(mx0, __shfl_xor_sync(0xffffffffu, mx0, 1));
        mx0 = fmaxf(mx0, __shfl_xor_sync(0xffffffffu, mx0, 2));
        mx1 = fmaxf(mx1, __shfl_xor_sync(0xffffffffu, mx1, 1));
        mx1 = fmaxf(mx1, __shfl_xor_sync(0xffffffffu, mx1, 2));
        const float mn0 = fmaxf(m0, mx0), mn1 = fmaxf(m1, mx1);
        const float cr0 = __expf(m0 - mn0), cr1 = __expf(m1 - mn1);
        float rs0 = 0.f, rs1 = 0.f;
#pragma unroll
        for (int nb = 0; nb < 8; nb++) {
            const int c = nb * 8 + 2 * ktid;
            float p0 = __expf(s[nb][0] - mn0);
            float p1 = __expf(s[nb][1] - mn0);
            float p2 = __expf(s[nb][2] - mn1);
            float p3 = __expf(s[nb][3] - mn1);
            rs0 += p0 + p1; rs1 += p2 + p3;
            Ps[(wq0 + g) * PS_STRIDE + c]     = f2tf32(p0);
            Ps[(wq0 + g) * PS_STRIDE + c + 1] = f2tf32(p1);
            Ps[(wq0 + g + 8) * PS_STRIDE + c]     = f2tf32(p2);
            Ps[(wq0 + g + 8) * PS_STRIDE + c + 1] = f2tf32(p3);
        }
        rs0 += __shfl_xor_sync(0xffffffffu, rs0, 1);
        rs0 += __shfl_xor_sync(0xffffffffu, rs0, 2);
        rs1 += __shfl_xor_sync(0xffffffffu, rs1, 1);
        rs1 += __shfl_xor_sync(0xffffffffu, rs1, 2);
        l0 = l0 * cr0 + rs0; l1 = l1 * cr1 + rs1;
        m0 = mn0; m1 = mn1;

        __syncthreads();   // all warps done reading K tile
        for (int i = tid; i < 2048; i += 128) {
            const int r = i >> 5, c4 = (i & 31) << 2;
            float4 v = *(const float4*)&g_qkv[(size_t)(kt * 64 + r) * QKVO +
                                              QSZ + KVSZ + kvh * HD + c4];
            uint32_t* dst = &KVs[r * QS_STRIDE + c4];
            dst[0] = f2tf32(v.x); dst[1] = f2tf32(v.y);
            dst[2] = f2tf32(v.z); dst[3] = f2tf32(v.w);
        }
        __syncthreads();   // V visible (Ps is warp-local, covered too)

#pragma unroll
        for (int nb = 0; nb < 16; nb++) {
            acc_o[nb][0] *= cr0; acc_o[nb][1] *= cr0;
            acc_o[nb][2] *= cr1; acc_o[nb][3] *= cr1;
        }

        // O += P V
#pragma unroll
        for (int kb = 0; kb < 8; kb++) {
            uint32_t a[4];
            a[0] = Ps[(wq0 + g) * PS_STRIDE + kb * 8 + ktid];
            a[1] = Ps[(wq0 + g + 8) * PS_STRIDE + kb * 8 + ktid];
            a[2] = Ps[(wq0 + g) * PS_STRIDE + kb * 8 + ktid + 4];
            a[3] = Ps[(wq0 + g + 8) * PS_STRIDE + kb * 8 + ktid + 4];
#pragma unroll
            for (int nb = 0; nb < 16; nb++) {
                uint32_t b[2];
                b[0] = KVs[(kb * 8 + ktid) * QS_STRIDE + nb * 8 + g];
                b[1] = KVs[(kb * 8 + ktid + 4) * QS_STRIDE + nb * 8 + g];
                mma_tf32(acc_o[nb], a, b);
            }
        }
    }

    const float il0 = 1.0f / l0, il1 = 1.0f / l1;
    const int row0 = bx * 64 + wq0 + g;
#pragma unroll
    for (int nb = 0; nb < 16; nb++) {
        const int col = h * HD + nb * 8 + 2 * ktid;
        float2 v0 = make_float2(acc_o[nb][0] * il0, acc_o[nb][1] * il0);
        float2 v1 = make_float2(acc_o[nb][2] * il1, acc_o[nb][3] * il1);
        *(float2*)&g_attn[(size_t)row0 * QSZ + col] = v0;
        *(float2*)&g_attn[(size_t)(row0 + 8) * QSZ + col] = v1;
    }
}

// ---------------- launch ----------------
extern "C" void kernel_launch(void* const* d_in, const int* in_sizes, int n_in,
                              void* d_out, int out_size)
{
    const float* hidden = (const float*)d_in[1];
    const float* w_qkv  = (const float*)d_in[2];
    const float* b_qkv  = (const float*)d_in[3];
    const float* qnw    = (const float*)d_in[4];
    const float* knw    = (const float*)d_in[5];
    const float* w_o    = (const float*)d_in[6];
    float* out = (float*)d_out;

    float *qkv_s, *attn_s;
    cudaGetSymbolAddress((void**)&qkv_s, g_qkv);
    cudaGetSymbolAddress((void**)&attn_s, g_attn);

    gemm_tf32_nt<true><<<dim3(QKVO / 128, TT / 128), 256>>>(
        hidden, w_qkv, b_qkv, qkv_s, TT, QKVO, HID);

    norm_rope_kernel<<<dim3(TT, NH + NKV), HD>>>(qnw, knw);

    cudaFuncSetAttribute(attn_tc_kernel,
                         cudaFuncAttributeMaxDynamicSharedMemorySize, ATTN_SMEM);
    attn_tc_kernel<<<dim3(TT / 64, NH), 128, ATTN_SMEM>>>();

    gemm_tf32_nt<false><<<dim3(HID / 128, TT / 128), 256>>>(
        attn_s, w_o, nullptr, out, TT, HID, HID);
}

// round 4
// speedup vs baseline: 3.9341x; 1.1823x over previous
#include <cuda_runtime.h>
#include <math.h>
#include <stdint.h>

#define TT   2048
#define HID  4096
#define NH   32
#define NKV  8
#define HD   128
#define QSZ  (NH * HD)          // 4096
#define KVSZ (NKV * HD)         // 1024
#define QKVO (QSZ + 2 * KVSZ)   // 6144

// ---------------- device scratch (allocation-free) ----------------
__device__ float    g_qkv[TT * QKVO];       // qkv output (f32 row-major)
__device__ float    g_q[TT * QSZ];          // normed+roped q
__device__ float    g_k[TT * KVSZ];         // normed+roped k
__device__ uint32_t g_attnq[TT * QSZ];      // attention out, tf32 quad layout
__device__ uint32_t g_hq[TT * HID];         // hidden, tf32 quad layout
__device__ uint32_t g_wqkvq[QKVO * HID];    // w_qkv, tf32 quad layout
__device__ uint32_t g_woq[HID * QSZ];       // w_o, tf32 quad layout

// ---------------- tf32 / async helpers ----------------
__device__ __forceinline__ uint32_t f2tf32(float x) {
    uint32_t u;
    asm("cvt.rna.tf32.f32 %0, %1;" : "=r"(u) : "f"(x));
    return u;
}
__device__ __forceinline__ void mma_tf32(float* d, const uint32_t* a, const uint32_t* b) {
    asm volatile(
        "mma.sync.aligned.m16n8k8.row.col.f32.tf32.tf32.f32 "
        "{%0,%1,%2,%3},{%4,%5,%6,%7},{%8,%9},{%0,%1,%2,%3};"
        : "+f"(d[0]), "+f"(d[1]), "+f"(d[2]), "+f"(d[3])
        : "r"(a[0]), "r"(a[1]), "r"(a[2]), "r"(a[3]), "r"(b[0]), "r"(b[1]));
}
__device__ __forceinline__ void cp16(uint32_t smem_addr, const void* gptr) {
    asm volatile("cp.async.cg.shared.global [%0], [%1], 16;"
                 :: "r"(smem_addr), "l"(gptr));
}

// ---------------- convert f32 row-major -> tf32 quad layout ----------------
// quad layout: word[ ((k8*(R/16)+row16)*32 + g*4+kt)*4 + (rh + 2*kh) ]
//   where r = row16*16 + rh*8 + g, c = k8*8 + kh*4 + kt
__global__ __launch_bounds__(256) void convert_quad(
    const float* __restrict__ src, uint32_t* __restrict__ dst, int R, int C)
{
    const int q = blockIdx.x * 256 + threadIdx.x;   // quad id
    const int lane = q & 31;
    const int t2 = q >> 5;
    const int row16 = t2 % (R >> 4);
    const int k8    = t2 / (R >> 4);
    const int g = lane >> 2, kt = lane & 3;
    const size_t r = row16 * 16 + g;
    const size_t c = k8 * 8 + kt;
    uint4 o;
    o.x = f2tf32(src[r * C + c]);
    o.y = f2tf32(src[(r + 8) * C + c]);
    o.z = f2tf32(src[r * C + c + 4]);
    o.w = f2tf32(src[(r + 8) * C + c + 4]);
    *(uint4*)&dst[(size_t)q * 4] = o;
}

// ---------------- quad-layout tf32 GEMM: C = A * B^T (+bias) ----------------
// 128x128 tile, BK=16, 8 warps (2x4), warp 64x32, cp.async 3-stage pipeline,
// LDS.128 fragment loads from fragment-major smem.
#define GEMM_SMEM (3 * 16384)
template <bool HAS_BIAS>
__global__ __launch_bounds__(256, 2) void gemm_quad(
    const uint32_t* __restrict__ Aq, const uint32_t* __restrict__ Bq,
    const float* __restrict__ bias, float* __restrict__ C,
    int M, int N, int K)
{
    extern __shared__ uint32_t sm[];
    const int tid  = threadIdx.x;
    const int lane = tid & 31;
    const int warp = tid >> 5;
    const int wm = (warp >> 2) * 64;
    const int wn = (warp & 3) * 32;
    const int m0 = blockIdx.y * 128, n0 = blockIdx.x * 128;
    const int g = lane >> 2, ktid = lane & 3;

    const uint32_t smem_base = (uint32_t)__cvta_generic_to_shared(sm);
    // per-thread cp.async dsts (s = 0,1 halves of the 16-k tile)
    const uint32_t dA0 = smem_base + (warp * 32 + lane) * 16;
    const uint32_t dA1 = smem_base + ((8 + warp) * 32 + lane) * 16;
    const uint32_t dB0 = smem_base + 8192 + (warp * 32 + lane) * 16;
    const uint32_t dB1 = smem_base + 8192 + ((8 + warp) * 32 + lane) * 16;
    const uint32_t* srcA = Aq + (size_t)(m0 / 16 + warp) * 128 + lane * 4;
    const uint32_t* srcB = Bq + (size_t)(n0 / 16 + warp) * 128 + lane * 4;
    const size_t sA = (size_t)M * 8;   // u32 per k8-slab
    const size_t sB = (size_t)N * 8;

    float acc[4][4][4];
#pragma unroll
    for (int i = 0; i < 4; i++)
#pragma unroll
        for (int j = 0; j < 4; j++)
#pragma unroll
            for (int c = 0; c < 4; c++) acc[i][j][c] = 0.f;

#define ISSUE(stage, k8)                                                 \
    do {                                                                 \
        const uint32_t so = (stage) * 16384;                             \
        cp16(dA0 + so, srcA + (size_t)(k8) * sA);                        \
        cp16(dA1 + so, srcA + (size_t)((k8) + 1) * sA);                  \
        cp16(dB0 + so, srcB + (size_t)(k8) * sB);                        \
        cp16(dB1 + so, srcB + (size_t)((k8) + 1) * sB);                  \
        asm volatile("cp.async.commit_group;");                          \
    } while (0)

    const int nkt = K / 16;
    ISSUE(0, 0);
    ISSUE(1, 2);

    const int arb = (warp >> 2) * 4;      // A row-block base for this warp
    const int bcb = (warp & 3) * 2;       // B col-block base

    for (int i = 0; i < nkt; i++) {
        if (i + 1 < nkt) { asm volatile("cp.async.wait_group 1;"); }
        else             { asm volatile("cp.async.wait_group 0;"); }
        __syncthreads();

        const int i2 = i + 2;
        if (i2 < nkt) ISSUE(i2 % 3, 2 * i2);

        const uint32_t* As = sm + (i % 3) * 4096;
        const uint32_t* Bs = As + 2048;
#pragma unroll
        for (int s = 0; s < 2; s++) {
            uint4 afq[4];
            const uint32_t* ab = As + ((s * 8 + arb) * 32 + lane) * 4;
#pragma unroll
            for (int mi = 0; mi < 4; mi++)
                afq[mi] = *(const uint4*)(ab + mi * 128);
            const uint32_t* bb = Bs + ((s * 8 + bcb) * 32 + lane) * 4;
            const uint4 bq0 = *(const uint4*)bb;
            const uint4 bq1 = *(const uint4*)(bb + 128);

            const uint32_t b0[2] = {bq0.x, bq0.z};
            const uint32_t b1[2] = {bq0.y, bq0.w};
            const uint32_t b2[2] = {bq1.x, bq1.z};
            const uint32_t b3[2] = {bq1.y, bq1.w};
#pragma unroll
            for (int mi = 0; mi < 4; mi++) {
                const uint32_t a[4] = {afq[mi].x, afq[mi].y, afq[mi].z, afq[mi].w};
                mma_tf32(acc[mi][0], a, b0);
                mma_tf32(acc[mi][1], a, b1);
                mma_tf32(acc[mi][2], a, b2);
                mma_tf32(acc[mi][3], a, b3);
            }
        }
        __syncthreads();
    }
#undef ISSUE

#pragma unroll
    for (int mi = 0; mi < 4; mi++) {
        const int row = m0 + wm + mi * 16 + g;
#pragma unroll
        for (int ni = 0; ni < 4; ni++) {
            const int col = n0 + wn + ni * 8 + 2 * ktid;
            float b0 = 0.f, b1 = 0.f;
            if (HAS_BIAS) { b0 = bias[col]; b1 = bias[col + 1]; }
            float2 v0 = make_float2(acc[mi][ni][0] + b0, acc[mi][ni][1] + b1);
            float2 v1 = make_float2(acc[mi][ni][2] + b0, acc[mi][ni][3] + b1);
            *(float2*)&C[(size_t)row * N + col] = v0;
            *(float2*)&C[(size_t)(row + 8) * N + col] = v1;
        }
    }
}

// ---------------- per-head RMSNorm + partial RoPE ----------------
__global__ void norm_rope_kernel(const float* __restrict__ qnw,
                                 const float* __restrict__ knw)
{
    const int t = blockIdx.x;
    const int h = blockIdx.y;
    const int d = threadIdx.x;
    const bool is_q = (h < NH);
    const int off = is_q ? (h * HD) : (QSZ + (h - NH) * HD);
    const float x = g_qkv[(size_t)t * QKVO + off + d];

    float s = x * x;
#pragma unroll
    for (int o = 16; o; o >>= 1) s += __shfl_xor_sync(0xffffffffu, s, o);
    __shared__ float red[4];
    if ((d & 31) == 0) red[d >> 5] = s;
    __syncthreads();
    const float sum = red[0] + red[1] + red[2] + red[3];
    const float r = rsqrtf(sum * (1.0f / HD) + 1e-5f);
    const float y = x * r * (is_q ? qnw[d] : knw[d]);

    __shared__ float sh[HD];
    sh[d] = y;
    __syncthreads();

    float outv = y;
    if (d < 64) {
        const int i = d & 31;
        const float inv_freq = powf(10000.0f, -(float)i * (1.0f / 32.0f));
        const float ang = (float)t * inv_freq;
        float sn, cs;
        sincosf(ang, &sn, &cs);
        if (d < 32) outv = sh[d] * cs - sh[d + 32] * sn;
        else        outv = sh[d] * cs + sh[d - 32] * sn;
    }
    if (is_q) g_q[(size_t)t * QSZ + h * HD + d] = outv;
    else      g_k[(size_t)t * KVSZ + (h - NH) * HD + d] = outv;
}

// ---------------- tensor-core causal flash attention (tf32) ----------------
#define QS_STRIDE 132
#define PS_STRIDE 68
#define ATTN_SMEM ((2 * 64 * QS_STRIDE + 64 * PS_STRIDE) * 4)

__global__ __launch_bounds__(128, 2) void attn_tc_kernel()
{
    extern __shared__ uint32_t smem_u[];
    uint32_t* Qs  = smem_u;
    uint32_t* KVs = smem_u + 64 * QS_STRIDE;
    uint32_t* Ps  = smem_u + 2 * 64 * QS_STRIDE;

    const int tid  = threadIdx.x;
    const int lane = tid & 31;
    const int warp = tid >> 5;
    const int g    = lane >> 2;
    const int ktid = lane & 3;
    const int wq0  = warp * 16;
    const int bx = blockIdx.x, h = blockIdx.y, kvh = h >> 2;
    const float scale = 0.0883883476483184f;

    for (int i = tid; i < 2048; i += 128) {
        const int r = i >> 5, c4 = (i & 31) << 2;
        float4 v = *(const float4*)&g_q[(size_t)(bx * 64 + r) * QSZ + h * HD + c4];
        uint32_t* dst = &Qs[r * QS_STRIDE + c4];
        dst[0] = f2tf32(v.x * scale); dst[1] = f2tf32(v.y * scale);
        dst[2] = f2tf32(v.z * scale); dst[3] = f2tf32(v.w * scale);
    }

    float m0 = -1e30f, m1 = -1e30f, l0 = 0.f, l1 = 0.f;
    float acc_o[16][4];
#pragma unroll
    for (int nb = 0; nb < 16; nb++)
#pragma unroll
        for (int c = 0; c < 4; c++) acc_o[nb][c] = 0.f;

    for (int kt = 0; kt <= bx; kt++) {
        __syncthreads();
        for (int i = tid; i < 2048; i += 128) {
            const int r = i >> 5, c4 = (i & 31) << 2;
            float4 v = *(const float4*)&g_k[(size_t)(kt * 64 + r) * KVSZ + kvh * HD + c4];
            uint32_t* dst = &KVs[r * QS_STRIDE + c4];
            dst[0] = f2tf32(v.x); dst[1] = f2tf32(v.y);
            dst[2] = f2tf32(v.z); dst[3] = f2tf32(v.w);
        }
        __syncthreads();

        float s[8][4];
#pragma unroll
        for (int nb = 0; nb < 8; nb++)
#pragma unroll
            for (int c = 0; c < 4; c++) s[nb][c] = 0.f;

#pragma unroll
        for (int kb = 0; kb < 16; kb++) {
            uint32_t a[4];
            a[0] = Qs[(wq0 + g) * QS_STRIDE + kb * 8 + ktid];
            a[1] = Qs[(wq0 + g + 8) * QS_STRIDE + kb * 8 + ktid];
            a[2] = Qs[(wq0 + g) * QS_STRIDE + kb * 8 + ktid + 4];
            a[3] = Qs[(wq0 + g + 8) * QS_STRIDE + kb * 8 + ktid + 4];
#pragma unroll
            for (int nb = 0; nb < 8; nb++) {
                uint32_t b[2];
                b[0] = KVs[(nb * 8 + g) * QS_STRIDE + kb * 8 + ktid];
                b[1] = KVs[(nb * 8 + g) * QS_STRIDE + kb * 8 + ktid + 4];
                mma_tf32(s[nb], a, b);
            }
        }

        if (kt == bx) {
            const int r0 = wq0 + g, r1 = r0 + 8;
#pragma unroll
            for (int nb = 0; nb < 8; nb++) {
                const int c = nb * 8 + 2 * ktid;
                if (c     > r0) s[nb][0] = -1e30f;
                if (c + 1 > r0) s[nb][1] = -1e30f;
                if (c     > r1) s[nb][2] = -1e30f;
                if (c + 1 > r1) s[nb][3] = -1e30f;
            }
        }

        float mx0 = -1e30f, mx1 = -1e30f;
#pragma unroll
        for (int nb = 0; nb < 8; nb++) {
            mx0 = fmaxf(mx0, fmaxf(s[nb][0], s[nb][1]));
            mx1 = fmaxf(mx1, fmaxf(s[nb][2], s[nb][3]));
        }
        mx0 = fmaxf(mx0, __shfl_xor_sync(0xffffffffu, mx0, 1));
        mx0 = fmaxf(mx0, __shfl_xor_sync(0xffffffffu, mx0, 2));
        mx1 = fmaxf(mx1, __shfl_xor_sync(0xffffffffu, mx1, 1));
        mx1 = fmaxf(mx1, __shfl_xor_sync(0xffffffffu, mx1, 2));
        const float mn0 = fmaxf(m0, mx0), mn1 = fmaxf(m1, mx1);
        const float cr0 = __expf(m0 - mn0), cr1 = __expf(m1 - mn1);
        float rs0 = 0.f, rs1 = 0.f;
#pragma unroll
        for (int nb = 0; nb < 8; nb++) {
            const int c = nb * 8 + 2 * ktid;
            float p0 = __expf(s[nb][0] - mn0);
            float p1 = __expf(s[nb][1] - mn0);
            float p2 = __expf(s[nb][2] - mn1);
            float p3 = __expf(s[nb][3] - mn1);
            rs0 += p0 + p1; rs1 += p2 + p3;
            Ps[(wq0 + g) * PS_STRIDE + c]     = f2tf32(p0);
            Ps[(wq0 + g) * PS_STRIDE + c + 1] = f2tf32(p1);
            Ps[(wq0 + g + 8) * PS_STRIDE + c]     = f2tf32(p2);
            Ps[(wq0 + g + 8) * PS_STRIDE + c + 1] = f2tf32(p3);
        }
        rs0 += __shfl_xor_sync(0xffffffffu, rs0, 1);
        rs0 += __shfl_xor_sync(0xffffffffu, rs0, 2);
        rs1 += __shfl_xor_sync(0xffffffffu, rs1, 1);
        rs1 += __shfl_xor_sync(0xffffffffu, rs1, 2);
        l0 = l0 * cr0 + rs0; l1 = l1 * cr1 + rs1;
        m0 = mn0; m1 = mn1;

        __syncthreads();
        for (int i = tid; i < 2048; i += 128) {
            const int r = i >> 5, c4 = (i & 31) << 2;
            float4 v = *(const float4*)&g_qkv[(size_t)(kt * 64 + r) * QKVO +
                                              QSZ + KVSZ + kvh * HD + c4];
            uint32_t* dst = &KVs[r * QS_STRIDE + c4];
            dst[0] = f2tf32(v.x); dst[1] = f2tf32(v.y);
            dst[2] = f2tf32(v.z); dst[3] = f2tf32(v.w);
        }
        __syncthreads();

#pragma unroll
        for (int nb = 0; nb < 16; nb++) {
            acc_o[nb][0] *= cr0; acc_o[nb][1] *= cr0;
            acc_o[nb][2] *= cr1; acc_o[nb][3] *= cr1;
        }

#pragma unroll
        for (int kb = 0; kb < 8; kb++) {
            uint32_t a[4];
            a[0] = Ps[(wq0 + g) * PS_STRIDE + kb * 8 + ktid];
            a[1] = Ps[(wq0 + g + 8) * PS_STRIDE + kb * 8 + ktid];
            a[2] = Ps[(wq0 + g) * PS_STRIDE + kb * 8 + ktid + 4];
            a[3] = Ps[(wq0 + g + 8) * PS_STRIDE + kb * 8 + ktid + 4];
#pragma unroll
            for (int nb = 0; nb < 16; nb++) {
                uint32_t b[2];
                b[0] = KVs[(kb * 8 + ktid) * QS_STRIDE + nb * 8 + g];
                b[1] = KVs[(kb * 8 + ktid + 4) * QS_STRIDE + nb * 8 + g];
                mma_tf32(acc_o[nb], a, b);
            }
        }
    }

    // epilogue: write O directly in tf32 quad layout (A' for O-proj GEMM)
    const float il0 = 1.0f / l0, il1 = 1.0f / l1;
    const int row16 = bx * 4 + warp;
    const int ktp = (2 * ktid) & 3;
    const int khp = ktid >> 1;
#pragma unroll
    for (int nb = 0; nb < 16; nb++) {
        const int k8 = h * 16 + nb;
        uint32_t* base = g_attnq + ((size_t)(k8 * (TT / 16) + row16) * 32) * 4;
        const int lane0 = g * 4 + ktp;
        base[lane0 * 4 + 2 * khp]           = f2tf32(acc_o[nb][0] * il0);
        base[(lane0 + 1) * 4 + 2 * khp]     = f2tf32(acc_o[nb][1] * il0);
        base[lane0 * 4 + 2 * khp + 1]       = f2tf32(acc_o[nb][2] * il1);
        base[(lane0 + 1) * 4 + 2 * khp + 1] = f2tf32(acc_o[nb][3] * il1);
    }
}

// ---------------- launch ----------------
extern "C" void kernel_launch(void* const* d_in, const int* in_sizes, int n_in,
                              void* d_out, int out_size)
{
    const float* hidden = (const float*)d_in[1];
    const float* w_qkv  = (const float*)d_in[2];
    const float* b_qkv  = (const float*)d_in[3];
    const float* qnw    = (const float*)d_in[4];
    const float* knw    = (const float*)d_in[5];
    const float* w_o    = (const float*)d_in[6];
    float* out = (float*)d_out;

    float *qkv_s;
    uint32_t *attnq_s, *hq_s, *wqkvq_s, *woq_s;
    cudaGetSymbolAddress((void**)&qkv_s, g_qkv);
    cudaGetSymbolAddress((void**)&attnq_s, g_attnq);
    cudaGetSymbolAddress((void**)&hq_s, g_hq);
    cudaGetSymbolAddress((void**)&wqkvq_s, g_wqkvq);
    cudaGetSymbolAddress((void**)&woq_s, g_woq);

    // 0) convert operands to tf32 quad layout
    convert_quad<<<TT * HID / 1024, 256>>>(hidden, hq_s, TT, HID);
    convert_quad<<<QKVO * HID / 1024, 256>>>(w_qkv, wqkvq_s, QKVO, HID);
    convert_quad<<<HID * QSZ / 1024, 256>>>(w_o, woq_s, HID, QSZ);

    cudaFuncSetAttribute(gemm_quad<true>,
                         cudaFuncAttributeMaxDynamicSharedMemorySize, GEMM_SMEM);
    cudaFuncSetAttribute(gemm_quad<false>,
                         cudaFuncAttributeMaxDynamicSharedMemorySize, GEMM_SMEM);

    // 1) QKV projection + bias
    gemm_quad<true><<<dim3(QKVO / 128, TT / 128), 256, GEMM_SMEM>>>(
        hq_s, wqkvq_s, b_qkv, qkv_s, TT, QKVO, HID);

    // 2) RMSNorm + RoPE
    norm_rope_kernel<<<dim3(TT, NH + NKV), HD>>>(qnw, knw);

    // 3) causal GQA flash attention (writes quad-layout output)
    cudaFuncSetAttribute(attn_tc_kernel,
                         cudaFuncAttributeMaxDynamicSharedMemorySize, ATTN_SMEM);
    attn_tc_kernel<<<dim3(TT / 64, NH), 128, ATTN_SMEM>>>();

    // 4) output projection
    gemm_quad<false><<<dim3(HID / 128, TT / 128), 256, GEMM_SMEM>>>(
        attnq_s, woq_s, nullptr, out, TT, HID, QSZ);
}

// round 6
// speedup vs baseline: 5.8999x; 1.4997x over previous
#include <cuda_runtime.h>
#include <cuda_fp16.h>
#include <math.h>
#include <stdint.h>

#define TT   2048
#define HID  4096
#define NH   32
#define NKV  8
#define HD   128
#define QSZ  (NH * HD)          // 4096
#define KVSZ (NKV * HD)         // 1024
#define QKVO (QSZ + 2 * KVSZ)   // 6144

// ---------------- device scratch (allocation-free) ----------------
__device__ float    g_qkv[TT * QKVO];          // qkv output (f32 row-major)
__device__ float    g_q[TT * QSZ];             // normed+roped q (f32)
__device__ float    g_k[TT * KVSZ];            // normed+roped k (f32)
__device__ uint32_t g_attnq16[TT * QSZ / 2];   // attn out, fp16 quad layout
__device__ uint32_t g_h16[TT * HID / 2];       // hidden, fp16 quad layout
__device__ uint32_t g_wqkv16[QKVO * HID / 2];  // w_qkv,  fp16 quad layout
__device__ uint32_t g_wo16[HID * QSZ / 2];     // w_o,    fp16 quad layout

// ---------------- helpers ----------------
__device__ __forceinline__ uint32_t f2tf32(float x) {
    uint32_t u;
    asm("cvt.rna.tf32.f32 %0, %1;" : "=r"(u) : "f"(x));
    return u;
}
__device__ __forceinline__ uint32_t packh2(float a, float b) {
    __half2 h = __floats2half2_rn(a, b);
    return *(uint32_t*)&h;
}
__device__ __forceinline__ void mma_tf32(float* d, const uint32_t* a, const uint32_t* b) {
    asm volatile(
        "mma.sync.aligned.m16n8k8.row.col.f32.tf32.tf32.f32 "
        "{%0,%1,%2,%3},{%4,%5,%6,%7},{%8,%9},{%0,%1,%2,%3};"
        : "+f"(d[0]), "+f"(d[1]), "+f"(d[2]), "+f"(d[3])
        : "r"(a[0]), "r"(a[1]), "r"(a[2]), "r"(a[3]), "r"(b[0]), "r"(b[1]));
}
__device__ __forceinline__ void mma_f16(float* d, const uint32_t* a, const uint32_t* b) {
    asm volatile(
        "mma.sync.aligned.m16n8k16.row.col.f32.f16.f16.f32 "
        "{%0,%1,%2,%3},{%4,%5,%6,%7},{%8,%9},{%0,%1,%2,%3};"
        : "+f"(d[0]), "+f"(d[1]), "+f"(d[2]), "+f"(d[3])
        : "r"(a[0]), "r"(a[1]), "r"(a[2]), "r"(a[3]), "r"(b[0]), "r"(b[1]));
}
__device__ __forceinline__ void cp16(uint32_t smem_addr, const void* gptr) {
    asm volatile("cp.async.cg.shared.global [%0], [%1], 16;"
                 :: "r"(smem_addr), "l"(gptr));
}

// ---------------- convert f32 row-major -> fp16 quad layout -----------------
// quad (16B) = mma m16n8k16 A-fragment for one lane:
//   w0 = (r,   c),(r,   c+1)   w1 = (r+8, c),(r+8, c+1)
//   w2 = (r,   c+8),(r, c+9)   w3 = (r+8, c+8),(r+8, c+9)
// with r = row16*16 + g, c = k16*16 + 2*ktid, lane = g*4 + ktid.
// dst index: (((k16*(R/16) + row16)*32) + lane)*4 words.
__global__ __launch_bounds__(256) void conv_quad_h(
    const float* __restrict__ src, uint32_t* __restrict__ dst, int R, int C)
{
    const int q = blockIdx.x * 256 + threadIdx.x;
    const int lane = q & 31;
    const int t2 = q >> 5;
    const int row16 = t2 % (R >> 4);
    const int k16   = t2 / (R >> 4);
    const int g = lane >> 2, t = lane & 3;
    const size_t r = row16 * 16 + g;
    const size_t c = k16 * 16 + 2 * t;
    const float* p0 = src + r * C + c;
    const float* p1 = src + (r + 8) * C + c;
    uint4 o;
    o.x = packh2(p0[0], p0[1]);
    o.y = packh2(p1[0], p1[1]);
    o.z = packh2(p0[8], p0[9]);
    o.w = packh2(p1[8], p1[9]);
    *(uint4*)&dst[(size_t)q * 4] = o;
}

// ---------------- fp16 quad GEMM: C[M,N] = A[M,K]*B[N,K]^T (+bias) ----------
// 128x128 tile, BK=32 (2 k16 slabs), 8 warps (2x4), warp 64x32,
// cp.async 3-stage pipeline, LDS.128 fragment loads, HMMA m16n8k16.
#define GEMM_SMEM (3 * 16384)
template <bool HAS_BIAS>
__global__ __launch_bounds__(256, 2) void gemm_h16(
    const uint32_t* __restrict__ Aq, const uint32_t* __restrict__ Bq,
    const float* __restrict__ bias, float* __restrict__ C,
    int M, int N, int K)
{
    extern __shared__ uint32_t sm[];
    const int tid  = threadIdx.x;
    const int lane = tid & 31;
    const int warp = tid >> 5;
    const int wm = (warp >> 2) * 64;
    const int wn = (warp & 3) * 32;
    const int m0 = blockIdx.y * 128, n0 = blockIdx.x * 128;
    const int g = lane >> 2, ktid = lane & 3;

    const uint32_t smem_base = (uint32_t)__cvta_generic_to_shared(sm);
    const uint32_t dA0 = smem_base + (warp * 32 + lane) * 16;
    const uint32_t dA1 = smem_base + ((8 + warp) * 32 + lane) * 16;
    const uint32_t dB0 = smem_base + 8192 + (warp * 32 + lane) * 16;
    const uint32_t dB1 = smem_base + 8192 + ((8 + warp) * 32 + lane) * 16;
    const uint32_t* srcA = Aq + (size_t)(m0 / 16 + warp) * 128 + lane * 4;
    const uint32_t* srcB = Bq + (size_t)(n0 / 16 + warp) * 128 + lane * 4;
    const size_t sA = (size_t)M * 8;   // u32 per k16-slab
    const size_t sB = (size_t)N * 8;

    float acc[4][4][4];
#pragma unroll
    for (int i = 0; i < 4; i++)
#pragma unroll
        for (int j = 0; j < 4; j++)
#pragma unroll
            for (int c = 0; c < 4; c++) acc[i][j][c] = 0.f;

#define ISSUE(stage, k16s)                                               \
    do {                                                                 \
        const uint32_t so = (stage) * 16384;                             \
        cp16(dA0 + so, srcA + (size_t)(k16s) * sA);                      \
        cp16(dA1 + so, srcA + (size_t)((k16s) + 1) * sA);                \
        cp16(dB0 + so, srcB + (size_t)(k16s) * sB);                      \
        cp16(dB1 + so, srcB + (size_t)((k16s) + 1) * sB);                \
        asm volatile("cp.async.commit_group;");                          \
    } while (0)

    const int nkt = K / 32;
    ISSUE(0, 0);
    ISSUE(1, 2);

    const int arb = (warp >> 2) * 4;
    const int bcb = (warp & 3) * 2;

    for (int i = 0; i < nkt; i++) {
        if (i + 1 < nkt) { asm volatile("cp.async.wait_group 1;"); }
        else             { asm volatile("cp.async.wait_group 0;"); }
        __syncthreads();

        const int i2 = i + 2;
        if (i2 < nkt) ISSUE(i2 % 3, 2 * i2);

        const uint32_t* As = sm + (i % 3) * 4096;
        const uint32_t* Bs = As + 2048;
#pragma unroll
        for (int s = 0; s < 2; s++) {
            uint4 afq[4];
            const uint32_t* ab = As + ((s * 8 + arb) * 32 + lane) * 4;
#pragma unroll
            for (int mi = 0; mi < 4; mi++)
                afq[mi] = *(const uint4*)(ab + mi * 128);
            const uint32_t* bb = Bs + ((s * 8 + bcb) * 32 + lane) * 4;
            const uint4 bq0 = *(const uint4*)bb;
            const uint4 bq1 = *(const uint4*)(bb + 128);

            const uint32_t b0[2] = {bq0.x, bq0.z};
            const uint32_t b1[2] = {bq0.y, bq0.w};
            const uint32_t b2[2] = {bq1.x, bq1.z};
            const uint32_t b3[2] = {bq1.y, bq1.w};
#pragma unroll
            for (int mi = 0; mi < 4; mi++) {
                const uint32_t a[4] = {afq[mi].x, afq[mi].y, afq[mi].z, afq[mi].w};
                mma_f16(acc[mi][0], a, b0);
                mma_f16(acc[mi][1], a, b1);
                mma_f16(acc[mi][2], a, b2);
                mma_f16(acc[mi][3], a, b3);
            }
        }
        __syncthreads();
    }
#undef ISSUE

#pragma unroll
    for (int mi = 0; mi < 4; mi++) {
        const int row = m0 + wm + mi * 16 + g;
#pragma unroll
        for (int ni = 0; ni < 4; ni++) {
            const int col = n0 + wn + ni * 8 + 2 * ktid;
            float b0 = 0.f, b1 = 0.f;
            if (HAS_BIAS) { b0 = bias[col]; b1 = bias[col + 1]; }
            float2 v0 = make_float2(acc[mi][ni][0] + b0, acc[mi][ni][1] + b1);
            float2 v1 = make_float2(acc[mi][ni][2] + b0, acc[mi][ni][3] + b1);
            *(float2*)&C[(size_t)row * N + col] = v0;
            *(float2*)&C[(size_t)(row + 8) * N + col] = v1;
        }
    }
}

// ---------------- per-head RMSNorm + partial RoPE ----------------
__global__ void norm_rope_kernel(const float* __restrict__ qnw,
                                 const float* __restrict__ knw)
{
    const int t = blockIdx.x;
    const int h = blockIdx.y;
    const int d = threadIdx.x;
    const bool is_q = (h < NH);
    const int off = is_q ? (h * HD) : (QSZ + (h - NH) * HD);
    const float x = g_qkv[(size_t)t * QKVO + off + d];

    float s = x * x;
#pragma unroll
    for (int o = 16; o; o >>= 1) s += __shfl_xor_sync(0xffffffffu, s, o);
    __shared__ float red[4];
    if ((d & 31) == 0) red[d >> 5] = s;
    __syncthreads();
    const float sum = red[0] + red[1] + red[2] + red[3];
    const float r = rsqrtf(sum * (1.0f / HD) + 1e-5f);
    const float y = x * r * (is_q ? qnw[d] : knw[d]);

    __shared__ float sh[HD];
    sh[d] = y;
    __syncthreads();

    float outv = y;
    if (d < 64) {
        const int i = d & 31;
        const float inv_freq = powf(10000.0f, -(float)i * (1.0f / 32.0f));
        const float ang = (float)t * inv_freq;
        float sn, cs;
        sincosf(ang, &sn, &cs);
        if (d < 32) outv = sh[d] * cs - sh[d + 32] * sn;
        else        outv = sh[d] * cs + sh[d - 32] * sn;
    }
    if (is_q) g_q[(size_t)t * QSZ + h * HD + d] = outv;
    else      g_k[(size_t)t * KVSZ + (h - NH) * HD + d] = outv;
}

// ---------------- tensor-core causal flash attention (tf32 mma.sync) --------
#define QS_STRIDE 132
#define PS_STRIDE 68
#define ATTN_SMEM ((2 * 64 * QS_STRIDE + 64 * PS_STRIDE) * 4)

__global__ __launch_bounds__(128, 2) void attn_tc_kernel()
{
    extern __shared__ uint32_t smem_u[];
    uint32_t* Qs  = smem_u;
    uint32_t* KVs = smem_u + 64 * QS_STRIDE;
    uint32_t* Ps  = smem_u + 2 * 64 * QS_STRIDE;

    const int tid  = threadIdx.x;
    const int lane = tid & 31;
    const int warp = tid >> 5;
    const int g    = lane >> 2;
    const int ktid = lane & 3;
    const int wq0  = warp * 16;
    const int bx = blockIdx.x, h = blockIdx.y, kvh = h >> 2;
    const float scale = 0.0883883476483184f;

    for (int i = tid; i < 2048; i += 128) {
        const int r = i >> 5, c4 = (i & 31) << 2;
        float4 v = *(const float4*)&g_q[(size_t)(bx * 64 + r) * QSZ + h * HD + c4];
        uint32_t* dst = &Qs[r * QS_STRIDE + c4];
        dst[0] = f2tf32(v.x * scale); dst[1] = f2tf32(v.y * scale);
        dst[2] = f2tf32(v.z * scale); dst[3] = f2tf32(v.w * scale);
    }

    float m0 = -1e30f, m1 = -1e30f, l0 = 0.f, l1 = 0.f;
    float acc_o[16][4];
#pragma unroll
    for (int nb = 0; nb < 16; nb++)
#pragma unroll
        for (int c = 0; c < 4; c++) acc_o[nb][c] = 0.f;

    for (int kt = 0; kt <= bx; kt++) {
        __syncthreads();
        for (int i = tid; i < 2048; i += 128) {
            const int r = i >> 5, c4 = (i & 31) << 2;
            float4 v = *(const float4*)&g_k[(size_t)(kt * 64 + r) * KVSZ + kvh * HD + c4];
            uint32_t* dst = &KVs[r * QS_STRIDE + c4];
            dst[0] = f2tf32(v.x); dst[1] = f2tf32(v.y);
            dst[2] = f2tf32(v.z); dst[3] = f2tf32(v.w);
        }
        __syncthreads();

        float s[8][4];
#pragma unroll
        for (int nb = 0; nb < 8; nb++)
#pragma unroll
            for (int c = 0; c < 4; c++) s[nb][c] = 0.f;

#pragma unroll
        for (int kb = 0; kb < 16; kb++) {
            uint32_t a[4];
            a[0] = Qs[(wq0 + g) * QS_STRIDE + kb * 8 + ktid];
            a[1] = Qs[(wq0 + g + 8) * QS_STRIDE + kb * 8 + ktid];
            a[2] = Qs[(wq0 + g) * QS_STRIDE + kb * 8 + ktid + 4];
            a[3] = Qs[(wq0 + g + 8) * QS_STRIDE + kb * 8 + ktid + 4];
#pragma unroll
            for (int nb = 0; nb < 8; nb++) {
                uint32_t b[2];
                b[0] = KVs[(nb * 8 + g) * QS_STRIDE + kb * 8 + ktid];
                b[1] = KVs[(nb * 8 + g) * QS_STRIDE + kb * 8 + ktid + 4];
                mma_tf32(s[nb], a, b);
            }
        }

        if (kt == bx) {
            const int r0 = wq0 + g, r1 = r0 + 8;
#pragma unroll
            for (int nb = 0; nb < 8; nb++) {
                const int c = nb * 8 + 2 * ktid;
                if (c     > r0) s[nb][0] = -1e30f;
                if (c + 1 > r0) s[nb][1] = -1e30f;
                if (c     > r1) s[nb][2] = -1e30f;
                if (c + 1 > r1) s[nb][3] = -1e30f;
            }
        }

        float mx0 = -1e30f, mx1 = -1e30f;
#pragma unroll
        for (int nb = 0; nb < 8; nb++) {
            mx0 = fmaxf(mx0, fmaxf(s[nb][0], s[nb][1]));
            mx1 = fmaxf(mx1, fmaxf(s[nb][2], s[nb][3]));
        }
        mx0 = fmaxf(mx0, __shfl_xor_sync(0xffffffffu, mx0, 1));
        mx0 = fmaxf(mx0, __shfl_xor_sync(0xffffffffu, mx0, 2));
        mx1 = fmaxf(mx1, __shfl_xor_sync(0xffffffffu, mx1, 1));
        mx1 = fmaxf(mx1, __shfl_xor_sync(0xffffffffu, mx1, 2));
        const float mn0 = fmaxf(m0, mx0), mn1 = fmaxf(m1, mx1);
        const float cr0 = __expf(m0 - mn0), cr1 = __expf(m1 - mn1);
        float rs0 = 0.f, rs1 = 0.f;
#pragma unroll
        for (int nb = 0; nb < 8; nb++) {
            const int c = nb * 8 + 2 * ktid;
            float p0 = __expf(s[nb][0] - mn0);
            float p1 = __expf(s[nb][1] - mn0);
            float p2 = __expf(s[nb][2] - mn1);
            float p3 = __expf(s[nb][3] - mn1);
            rs0 += p0 + p1; rs1 += p2 + p3;
            Ps[(wq0 + g) * PS_STRIDE + c]     = f2tf32(p0);
            Ps[(wq0 + g) * PS_STRIDE + c + 1] = f2tf32(p1);
            Ps[(wq0 + g + 8) * PS_STRIDE + c]     = f2tf32(p2);
            Ps[(wq0 + g + 8) * PS_STRIDE + c + 1] = f2tf32(p3);
        }
        rs0 += __shfl_xor_sync(0xffffffffu, rs0, 1);
        rs0 += __shfl_xor_sync(0xffffffffu, rs0, 2);
        rs1 += __shfl_xor_sync(0xffffffffu, rs1, 1);
        rs1 += __shfl_xor_sync(0xffffffffu, rs1, 2);
        l0 = l0 * cr0 + rs0; l1 = l1 * cr1 + rs1;
        m0 = mn0; m1 = mn1;

        __syncthreads();
        for (int i = tid; i < 2048; i += 128) {
            const int r = i >> 5, c4 = (i & 31) << 2;
            float4 v = *(const float4*)&g_qkv[(size_t)(kt * 64 + r) * QKVO +
                                              QSZ + KVSZ + kvh * HD + c4];
            uint32_t* dst = &KVs[r * QS_STRIDE + c4];
            dst[0] = f2tf32(v.x); dst[1] = f2tf32(v.y);
            dst[2] = f2tf32(v.z); dst[3] = f2tf32(v.w);
        }
        __syncthreads();

#pragma unroll
        for (int nb = 0; nb < 16; nb++) {
            acc_o[nb][0] *= cr0; acc_o[nb][1] *= cr0;
            acc_o[nb][2] *= cr1; acc_o[nb][3] *= cr1;
        }

#pragma unroll
        for (int kb = 0; kb < 8; kb++) {
            uint32_t a[4];
            a[0] = Ps[(wq0 + g) * PS_STRIDE + kb * 8 + ktid];
            a[1] = Ps[(wq0 + g + 8) * PS_STRIDE + kb * 8 + ktid];
            a[2] = Ps[(wq0 + g) * PS_STRIDE + kb * 8 + ktid + 4];
            a[3] = Ps[(wq0 + g + 8) * PS_STRIDE + kb * 8 + ktid + 4];
#pragma unroll
            for (int nb = 0; nb < 16; nb++) {
                uint32_t b[2];
                b[0] = KVs[(kb * 8 + ktid) * QS_STRIDE + nb * 8 + g];
                b[1] = KVs[(kb * 8 + ktid + 4) * QS_STRIDE + nb * 8 + g];
                mma_tf32(acc_o[nb], a, b);
            }
        }
    }

    // epilogue: write O directly as fp16 quad layout (A of the O-proj GEMM).
    // global row = bx*64 + wq0 + g  (and +8)  ->  row16 = bx*4 + warp.
    const float il0 = 1.0f / l0, il1 = 1.0f / l1;
    const int row16 = bx * 4 + warp;
#pragma unroll
    for (int nbp = 0; nbp < 8; nbp++) {
        const int nbe = 2 * nbp, nbo = 2 * nbp + 1;
        const int k16 = h * 8 + nbp;
        uint4 o;
        o.x = packh2(acc_o[nbe][0] * il0, acc_o[nbe][1] * il0);  // (g,   c,c+1)
        o.y = packh2(acc_o[nbe][2] * il1, acc_o[nbe][3] * il1);  // (g+8, c,c+1)
        o.z = packh2(acc_o[nbo][0] * il0, acc_o[nbo][1] * il0);  // (g,   c+8,c+9)
        o.w = packh2(acc_o[nbo][2] * il1, acc_o[nbo][3] * il1);  // (g+8, c+8,c+9)
        const size_t quad = ((size_t)k16 * (TT / 16) + row16) * 32 + lane;
        *(uint4*)&g_attnq16[quad * 4] = o;
    }
}

// ---------------- launch ----------------
extern "C" void kernel_launch(void* const* d_in, const int* in_sizes, int n_in,
                              void* d_out, int out_size)
{
    const float* hidden = (const float*)d_in[1];
    const float* w_qkv  = (const float*)d_in[2];
    const float* b_qkv  = (const float*)d_in[3];
    const float* qnw    = (const float*)d_in[4];
    const float* knw    = (const float*)d_in[5];
    const float* w_o    = (const float*)d_in[6];
    float* out = (float*)d_out;

    float *qkv_s;
    uint32_t *attnq_s, *h16_s, *wqkv16_s, *wo16_s;
    cudaGetSymbolAddress((void**)&qkv_s, g_qkv);
    cudaGetSymbolAddress((void**)&attnq_s, g_attnq16);
    cudaGetSymbolAddress((void**)&h16_s, g_h16);
    cudaGetSymbolAddress((void**)&wqkv16_s, g_wqkv16);
    cudaGetSymbolAddress((void**)&wo16_s, g_wo16);

    // 0) convert GEMM operands to fp16 quad layout
    conv_quad_h<<<(TT * HID) / 2048, 256>>>(hidden, h16_s, TT, HID);
    conv_quad_h<<<(QKVO * HID) / 2048, 256>>>(w_qkv, wqkv16_s, QKVO, HID);
    conv_quad_h<<<(HID * QSZ) / 2048, 256>>>(w_o, wo16_s, HID, QSZ);

    cudaFuncSetAttribute(gemm_h16<true>,
                         cudaFuncAttributeMaxDynamicSharedMemorySize, GEMM_SMEM);
    cudaFuncSetAttribute(gemm_h16<false>,
                         cudaFuncAttributeMaxDynamicSharedMemorySize, GEMM_SMEM);

    // 1) QKV projection + bias (fp16 HMMA)
    gemm_h16<true><<<dim3(QKVO / 128, TT / 128), 256, GEMM_SMEM>>>(
        h16_s, wqkv16_s, b_qkv, qkv_s, TT, QKVO, HID);

    // 2) RMSNorm + RoPE
    norm_rope_kernel<<<dim3(TT, NH + NKV), HD>>>(qnw, knw);

    // 3) causal GQA flash attention (tf32; fp16-quad epilogue)
    cudaFuncSetAttribute(attn_tc_kernel,
                         cudaFuncAttributeMaxDynamicSharedMemorySize, ATTN_SMEM);
    attn_tc_kernel<<<dim3(TT / 64, NH), 128, ATTN_SMEM>>>();

    // 4) output projection (fp16 HMMA)
    gemm_h16<false><<<dim3(HID / 128, TT / 128), 256, GEMM_SMEM>>>(
        attnq_s, wo16_s, nullptr, out, TT, HID, QSZ);
}

// round 7
// speedup vs baseline: 7.8175x; 1.3250x over previous
#include <cuda_runtime.h>
#include <cuda_fp16.h>
#include <math.h>
#include <stdint.h>

#define TT   2048
#define HID  4096
#define NH   32
#define NKV  8
#define HD   128
#define QSZ  (NH * HD)          // 4096
#define KVSZ (NKV * HD)         // 1024
#define QKVO (QSZ + 2 * KVSZ)   // 6144

// ---------------- device scratch (allocation-free) ----------------
__device__ float    g_qkv[TT * QKVO];          // qkv output (f32 row-major)
__device__ uint32_t g_qh[TT * QSZ / 2];        // normed+roped+scaled q (half2)
__device__ uint32_t g_kh[TT * KVSZ / 2];       // normed+roped k (half2)
__device__ uint32_t g_vh[TT * KVSZ / 2];       // v (half2)
__device__ uint32_t g_attnq16[TT * QSZ / 2];   // attn out, fp16 quad layout
__device__ uint32_t g_h16[TT * HID / 2];       // hidden, fp16 quad layout
__device__ uint32_t g_wqkv16[QKVO * HID / 2];  // w_qkv,  fp16 quad layout
__device__ uint32_t g_wo16[HID * QSZ / 2];     // w_o,    fp16 quad layout

// ---------------- helpers ----------------
__device__ __forceinline__ uint32_t packh2(float a, float b) {
    __half2 h = __floats2half2_rn(a, b);
    return *(uint32_t*)&h;
}
__device__ __forceinline__ void mma_f16(float* d, const uint32_t* a, const uint32_t* b) {
    asm volatile(
        "mma.sync.aligned.m16n8k16.row.col.f32.f16.f16.f32 "
        "{%0,%1,%2,%3},{%4,%5,%6,%7},{%8,%9},{%0,%1,%2,%3};"
        : "+f"(d[0]), "+f"(d[1]), "+f"(d[2]), "+f"(d[3])
        : "r"(a[0]), "r"(a[1]), "r"(a[2]), "r"(a[3]), "r"(b[0]), "r"(b[1]));
}
__device__ __forceinline__ void cp16(uint32_t smem_addr, const void* gptr) {
    asm volatile("cp.async.cg.shared.global [%0], [%1], 16;"
                 :: "r"(smem_addr), "l"(gptr));
}
__device__ __forceinline__ void ldsm_x2_trans(uint32_t& r0, uint32_t& r1, uint32_t addr) {
    asm volatile("ldmatrix.sync.aligned.m8n8.x2.trans.shared.b16 {%0,%1}, [%2];"
                 : "=r"(r0), "=r"(r1) : "r"(addr));
}

// ---------------- convert f32 row-major -> fp16 quad layout -----------------
__global__ __launch_bounds__(256) void conv_quad_h(
    const float* __restrict__ src, uint32_t* __restrict__ dst, int R, int C)
{
    const int q = blockIdx.x * 256 + threadIdx.x;
    const int lane = q & 31;
    const int t2 = q >> 5;
    const int row16 = t2 % (R >> 4);
    const int k16   = t2 / (R >> 4);
    const int g = lane >> 2, t = lane & 3;
    const size_t r = row16 * 16 + g;
    const size_t c = k16 * 16 + 2 * t;
    const float* p0 = src + r * C + c;
    const float* p1 = src + (r + 8) * C + c;
    uint4 o;
    o.x = packh2(p0[0], p0[1]);
    o.y = packh2(p1[0], p1[1]);
    o.z = packh2(p0[8], p0[9]);
    o.w = packh2(p1[8], p1[9]);
    *(uint4*)&dst[(size_t)q * 4] = o;
}

// ---------------- fp16 quad GEMM (unchanged from R6) ----------------
#define GEMM_SMEM (3 * 16384)
template <bool HAS_BIAS>
__global__ __launch_bounds__(256, 2) void gemm_h16(
    const uint32_t* __restrict__ Aq, const uint32_t* __restrict__ Bq,
    const float* __restrict__ bias, float* __restrict__ C,
    int M, int N, int K)
{
    extern __shared__ uint32_t sm[];
    const int tid  = threadIdx.x;
    const int lane = tid & 31;
    const int warp = tid >> 5;
    const int wm = (warp >> 2) * 64;
    const int wn = (warp & 3) * 32;
    const int m0 = blockIdx.y * 128, n0 = blockIdx.x * 128;
    const int g = lane >> 2, ktid = lane & 3;

    const uint32_t smem_base = (uint32_t)__cvta_generic_to_shared(sm);
    const uint32_t dA0 = smem_base + (warp * 32 + lane) * 16;
    const uint32_t dA1 = smem_base + ((8 + warp) * 32 + lane) * 16;
    const uint32_t dB0 = smem_base + 8192 + (warp * 32 + lane) * 16;
    const uint32_t dB1 = smem_base + 8192 + ((8 + warp) * 32 + lane) * 16;
    const uint32_t* srcA = Aq + (size_t)(m0 / 16 + warp) * 128 + lane * 4;
    const uint32_t* srcB = Bq + (size_t)(n0 / 16 + warp) * 128 + lane * 4;
    const size_t sA = (size_t)M * 8;
    const size_t sB = (size_t)N * 8;

    float acc[4][4][4];
#pragma unroll
    for (int i = 0; i < 4; i++)
#pragma unroll
        for (int j = 0; j < 4; j++)
#pragma unroll
            for (int c = 0; c < 4; c++) acc[i][j][c] = 0.f;

#define ISSUE(stage, k16s)                                               \
    do {                                                                 \
        const uint32_t so = (stage) * 16384;                             \
        cp16(dA0 + so, srcA + (size_t)(k16s) * sA);                      \
        cp16(dA1 + so, srcA + (size_t)((k16s) + 1) * sA);                \
        cp16(dB0 + so, srcB + (size_t)(k16s) * sB);                      \
        cp16(dB1 + so, srcB + (size_t)((k16s) + 1) * sB);                \
        asm volatile("cp.async.commit_group;");                          \
    } while (0)

    const int nkt = K / 32;
    ISSUE(0, 0);
    ISSUE(1, 2);

    const int arb = (warp >> 2) * 4;
    const int bcb = (warp & 3) * 2;

    for (int i = 0; i < nkt; i++) {
        if (i + 1 < nkt) { asm volatile("cp.async.wait_group 1;"); }
        else             { asm volatile("cp.async.wait_group 0;"); }
        __syncthreads();

        const int i2 = i + 2;
        if (i2 < nkt) ISSUE(i2 % 3, 2 * i2);

        const uint32_t* As = sm + (i % 3) * 4096;
        const uint32_t* Bs = As + 2048;
#pragma unroll
        for (int s = 0; s < 2; s++) {
            uint4 afq[4];
            const uint32_t* ab = As + ((s * 8 + arb) * 32 + lane) * 4;
#pragma unroll
            for (int mi = 0; mi < 4; mi++)
                afq[mi] = *(const uint4*)(ab + mi * 128);
            const uint32_t* bb = Bs + ((s * 8 + bcb) * 32 + lane) * 4;
            const uint4 bq0 = *(const uint4*)bb;
            const uint4 bq1 = *(const uint4*)(bb + 128);

            const uint32_t b0[2] = {bq0.x, bq0.z};
            const uint32_t b1[2] = {bq0.y, bq0.w};
            const uint32_t b2[2] = {bq1.x, bq1.z};
            const uint32_t b3[2] = {bq1.y, bq1.w};
#pragma unroll
            for (int mi = 0; mi < 4; mi++) {
                const uint32_t a[4] = {afq[mi].x, afq[mi].y, afq[mi].z, afq[mi].w};
                mma_f16(acc[mi][0], a, b0);
                mma_f16(acc[mi][1], a, b1);
                mma_f16(acc[mi][2], a, b2);
                mma_f16(acc[mi][3], a, b3);
            }
        }
        __syncthreads();
    }
#undef ISSUE

#pragma unroll
    for (int mi = 0; mi < 4; mi++) {
        const int row = m0 + wm + mi * 16 + g;
#pragma unroll
        for (int ni = 0; ni < 4; ni++) {
            const int col = n0 + wn + ni * 8 + 2 * ktid;
            float b0 = 0.f, b1 = 0.f;
            if (HAS_BIAS) { b0 = bias[col]; b1 = bias[col + 1]; }
            float2 v0 = make_float2(acc[mi][ni][0] + b0, acc[mi][ni][1] + b1);
            float2 v1 = make_float2(acc[mi][ni][2] + b0, acc[mi][ni][3] + b1);
            *(float2*)&C[(size_t)row * N + col] = v0;
            *(float2*)&C[(size_t)(row + 8) * N + col] = v1;
        }
    }
}

// ------- per-head RMSNorm + RoPE -> packed fp16 (q scaled); V pack ---------
// grid (T, 48): h<32 q, 32..39 k, 40..47 v(pack only). 128 threads.
__global__ void norm_rope_kernel(const float* __restrict__ qnw,
                                 const float* __restrict__ knw)
{
    const int t = blockIdx.x;
    const int h = blockIdx.y;
    const int d = threadIdx.x;
    float outv;

    if (h < 40) {
        const bool is_q = (h < NH);
        const int off = is_q ? (h * HD) : (QSZ + (h - NH) * HD);
        const float x = g_qkv[(size_t)t * QKVO + off + d];

        float s = x * x;
#pragma unroll
        for (int o = 16; o; o >>= 1) s += __shfl_xor_sync(0xffffffffu, s, o);
        __shared__ float red[4];
        if ((d & 31) == 0) red[d >> 5] = s;
        __syncthreads();
        const float sum = red[0] + red[1] + red[2] + red[3];
        const float r = rsqrtf(sum * (1.0f / HD) + 1e-5f);
        const float y = x * r * (is_q ? qnw[d] : knw[d]);

        __shared__ float sh[HD];
        sh[d] = y;
        __syncthreads();

        outv = y;
        if (d < 64) {
            const int i = d & 31;
            const float inv_freq = powf(10000.0f, -(float)i * (1.0f / 32.0f));
            const float ang = (float)t * inv_freq;
            float sn, cs;
            sincosf(ang, &sn, &cs);
            if (d < 32) outv = sh[d] * cs - sh[d + 32] * sn;
            else        outv = sh[d] * cs + sh[d - 32] * sn;
        }
        if (is_q) outv *= 0.0883883476483184f;   // fold 1/sqrt(HD)
    } else {
        outv = g_qkv[(size_t)t * QKVO + QSZ + KVSZ + (h - 40) * HD + d];
    }

    const float other = __shfl_down_sync(0xffffffffu, outv, 1);
    if ((d & 1) == 0) {
        const uint32_t w = packh2(outv, other);
        const int wd = d >> 1;
        if (h < NH)       g_qh[(size_t)t * (QSZ / 2) + h * 64 + wd] = w;
        else if (h < 40)  g_kh[(size_t)t * (KVSZ / 2) + (h - NH) * 64 + wd] = w;
        else              g_vh[(size_t)t * (KVSZ / 2) + (h - 40) * 64 + wd] = w;
    }
}

// ---------------- fp16 tensor-core causal flash attention -------------------
// 64 q x 64 keys per tile, 4 warps x 16 q-rows, mma m16n8k16,
// V B-fragments via ldmatrix.x2.trans.
#define AQS 68                         // row stride (half2 words) for Q/K/V
#define APS 36                         // row stride for P
#define Q_OFF 0
#define K_OFF (64 * AQS)               // 4352
#define V_OFF (2 * 64 * AQS)           // 8704
#define P_OFF (3 * 64 * AQS)           // 13056
#define ATTN_SMEM ((3 * 64 * AQS + 64 * APS) * 4)   // 61440 B

__global__ __launch_bounds__(128, 2) void attn_h16_kernel()
{
    extern __shared__ uint32_t smem_u[];
    const int tid  = threadIdx.x;
    const int lane = tid & 31;
    const int warp = tid >> 5;
    const int g    = lane >> 2;
    const int t4   = lane & 3;
    const int wq0  = warp * 16;
    const int bx = blockIdx.x, h = blockIdx.y, kvh = h >> 2;

    const uint32_t sb = (uint32_t)__cvta_generic_to_shared(smem_u);
    const uint32_t vb = sb + (V_OFF + (lane & 15) * AQS) * 4;   // ldmatrix rows

    // Q tile (pre-scaled fp16)
    for (int i = tid; i < 1024; i += 128) {
        const int r = i >> 4, w4 = (i & 15) << 2;
        uint4 v = *(const uint4*)&g_qh[(size_t)(bx * 64 + r) * (QSZ / 2) + h * 64 + w4];
        *(uint4*)&smem_u[Q_OFF + r * AQS + w4] = v;
    }

    float m0 = -1e30f, m1 = -1e30f, l0 = 0.f, l1 = 0.f;
    float acc_o[16][4];
#pragma unroll
    for (int nb = 0; nb < 16; nb++)
#pragma unroll
        for (int c = 0; c < 4; c++) acc_o[nb][c] = 0.f;

    for (int kt = 0; kt <= bx; kt++) {
        __syncthreads();   // previous iter done reading K/V; Q visible on first
        for (int i = tid; i < 1024; i += 128) {
            const int r = i >> 4, w4 = (i & 15) << 2;
            const size_t goff = (size_t)(kt * 64 + r) * (KVSZ / 2) + kvh * 64 + w4;
            uint4 kw = *(const uint4*)&g_kh[goff];
            *(uint4*)&smem_u[K_OFF + r * AQS + w4] = kw;
            uint4 vw = *(const uint4*)&g_vh[goff];
            *(uint4*)&smem_u[V_OFF + r * AQS + w4] = vw;
        }
        __syncthreads();

        // S = Q K^T
        float s[8][4];
#pragma unroll
        for (int nb = 0; nb < 8; nb++)
#pragma unroll
            for (int c = 0; c < 4; c++) s[nb][c] = 0.f;

#pragma unroll
        for (int kb = 0; kb < 8; kb++) {
            uint32_t a[4];
            a[0] = smem_u[Q_OFF + (wq0 + g) * AQS + kb * 8 + t4];
            a[1] = smem_u[Q_OFF + (wq0 + g + 8) * AQS + kb * 8 + t4];
            a[2] = smem_u[Q_OFF + (wq0 + g) * AQS + kb * 8 + t4 + 4];
            a[3] = smem_u[Q_OFF + (wq0 + g + 8) * AQS + kb * 8 + t4 + 4];
#pragma unroll
            for (int nb = 0; nb < 8; nb++) {
                uint32_t b[2];
                b[0] = smem_u[K_OFF + (nb * 8 + g) * AQS + kb * 8 + t4];
                b[1] = smem_u[K_OFF + (nb * 8 + g) * AQS + kb * 8 + t4 + 4];
                mma_f16(s[nb], a, b);
            }
        }

        // causal mask on diagonal tile
        if (kt == bx) {
            const int r0 = wq0 + g, r1 = r0 + 8;
#pragma unroll
            for (int nb = 0; nb < 8; nb++) {
                const int c = nb * 8 + 2 * t4;
                if (c     > r0) s[nb][0] = -1e30f;
                if (c + 1 > r0) s[nb][1] = -1e30f;
                if (c     > r1) s[nb][2] = -1e30f;
                if (c + 1 > r1) s[nb][3] = -1e30f;
            }
        }

        // online softmax
        float mx0 = -1e30f, mx1 = -1e30f;
#pragma unroll
        for (int nb = 0; nb < 8; nb++) {
            mx0 = fmaxf(mx0, fmaxf(s[nb][0], s[nb][1]));
            mx1 = fmaxf(mx1, fmaxf(s[nb][2], s[nb][3]));
        }
        mx0 = fmaxf(mx0, __shfl_xor_sync(0xffffffffu, mx0, 1));
        mx0 = fmaxf(mx0, __shfl_xor_sync(0xffffffffu, mx0, 2));
        mx1 = fmaxf(mx1, __shfl_xor_sync(0xffffffffu, mx1, 1));
        mx1 = fmaxf(mx1, __shfl_xor_sync(0xffffffffu, mx1, 2));
        const float mn0 = fmaxf(m0, mx0), mn1 = fmaxf(m1, mx1);
        const float cr0 = __expf(m0 - mn0), cr1 = __expf(m1 - mn1);
        float rs0 = 0.f, rs1 = 0.f;
#pragma unroll
        for (int nb = 0; nb < 8; nb++) {
            float p0 = __expf(s[nb][0] - mn0);
            float p1 = __expf(s[nb][1] - mn0);
            float p2 = __expf(s[nb][2] - mn1);
            float p3 = __expf(s[nb][3] - mn1);
            rs0 += p0 + p1; rs1 += p2 + p3;
            smem_u[P_OFF + (wq0 + g) * APS + nb * 4 + t4]     = packh2(p0, p1);
            smem_u[P_OFF + (wq0 + g + 8) * APS + nb * 4 + t4] = packh2(p2, p3);
        }
        rs0 += __shfl_xor_sync(0xffffffffu, rs0, 1);
        rs0 += __shfl_xor_sync(0xffffffffu, rs0, 2);
        rs1 += __shfl_xor_sync(0xffffffffu, rs1, 1);
        rs1 += __shfl_xor_sync(0xffffffffu, rs1, 2);
        l0 = l0 * cr0 + rs0; l1 = l1 * cr1 + rs1;
        m0 = mn0; m1 = mn1;
        __syncwarp();   // P visible within the warp

#pragma unroll
        for (int nb = 0; nb < 16; nb++) {
            acc_o[nb][0] *= cr0; acc_o[nb][1] *= cr0;
            acc_o[nb][2] *= cr1; acc_o[nb][3] *= cr1;
        }

        // O += P V   (V B-frags via ldmatrix.trans)
#pragma unroll
        for (int kb = 0; kb < 4; kb++) {
            uint32_t a[4];
            a[0] = smem_u[P_OFF + (wq0 + g) * APS + kb * 8 + t4];
            a[1] = smem_u[P_OFF + (wq0 + g + 8) * APS + kb * 8 + t4];
            a[2] = smem_u[P_OFF + (wq0 + g) * APS + kb * 8 + t4 + 4];
            a[3] = smem_u[P_OFF + (wq0 + g + 8) * APS + kb * 8 + t4 + 4];
            const uint32_t vkb = vb + kb * 16 * AQS * 4;
#pragma unroll
            for (int nb = 0; nb < 16; nb++) {
                uint32_t b[2];
                ldsm_x2_trans(b[0], b[1], vkb + nb * 16);
                mma_f16(acc_o[nb], a, b);
            }
        }
    }

    // epilogue: write O directly as fp16 quad layout (A of the O-proj GEMM)
    const float il0 = 1.0f / l0, il1 = 1.0f / l1;
    const int row16 = bx * 4 + warp;
#pragma unroll
    for (int nbp = 0; nbp < 8; nbp++) {
        const int nbe = 2 * nbp, nbo = 2 * nbp + 1;
        const int k16 = h * 8 + nbp;
        uint4 o;
        o.x = packh2(acc_o[nbe][0] * il0, acc_o[nbe][1] * il0);
        o.y = packh2(acc_o[nbe][2] * il1, acc_o[nbe][3] * il1);
        o.z = packh2(acc_o[nbo][0] * il0, acc_o[nbo][1] * il0);
        o.w = packh2(acc_o[nbo][2] * il1, acc_o[nbo][3] * il1);
        const size_t quad = ((size_t)k16 * (TT / 16) + row16) * 32 + lane;
        *(uint4*)&g_attnq16[quad * 4] = o;
    }
}

// ---------------- launch ----------------
extern "C" void kernel_launch(void* const* d_in, const int* in_sizes, int n_in,
                              void* d_out, int out_size)
{
    const float* hidden = (const float*)d_in[1];
    const float* w_qkv  = (const float*)d_in[2];
    const float* b_qkv  = (const float*)d_in[3];
    const float* qnw    = (const float*)d_in[4];
    const float* knw    = (const float*)d_in[5];
    const float* w_o    = (const float*)d_in[6];
    float* out = (float*)d_out;

    float *qkv_s;
    uint32_t *attnq_s, *h16_s, *wqkv16_s, *wo16_s;
    cudaGetSymbolAddress((void**)&qkv_s, g_qkv);
    cudaGetSymbolAddress((void**)&attnq_s, g_attnq16);
    cudaGetSymbolAddress((void**)&h16_s, g_h16);
    cudaGetSymbolAddress((void**)&wqkv16_s, g_wqkv16);
    cudaGetSymbolAddress((void**)&wo16_s, g_wo16);

    // 0) convert GEMM operands to fp16 quad layout
    conv_quad_h<<<(TT * HID) / 2048, 256>>>(hidden, h16_s, TT, HID);
    conv_quad_h<<<(QKVO * HID) / 2048, 256>>>(w_qkv, wqkv16_s, QKVO, HID);
    conv_quad_h<<<(HID * QSZ) / 2048, 256>>>(w_o, wo16_s, HID, QSZ);

    cudaFuncSetAttribute(gemm_h16<true>,
                         cudaFuncAttributeMaxDynamicSharedMemorySize, GEMM_SMEM);
    cudaFuncSetAttribute(gemm_h16<false>,
                         cudaFuncAttributeMaxDynamicSharedMemorySize, GEMM_SMEM);

    // 1) QKV projection + bias (fp16 HMMA)
    gemm_h16<true><<<dim3(QKVO / 128, TT / 128), 256, GEMM_SMEM>>>(
        h16_s, wqkv16_s, b_qkv, qkv_s, TT, QKVO, HID);

    // 2) RMSNorm + RoPE + fp16 pack (q scaled), V fp16 pack
    norm_rope_kernel<<<dim3(TT, 48), HD>>>(qnw, knw);

    // 3) causal GQA flash attention (fp16 HMMA + ldmatrix.trans V)
    cudaFuncSetAttribute(attn_h16_kernel,
                         cudaFuncAttributeMaxDynamicSharedMemorySize, ATTN_SMEM);
    attn_h16_kernel<<<dim3(TT / 64, NH), 128, ATTN_SMEM>>>();

    // 4) output projection (fp16 HMMA)
    gemm_h16<false><<<dim3(HID / 128, TT / 128), 256, GEMM_SMEM>>>(
        attnq_s, wo16_s, nullptr, out, TT, HID, QSZ);
}